// round 9
// baseline (speedup 1.0000x reference)
#include <cuda_runtime.h>
#include <cuda_fp16.h>
#include <math.h>
#include <stdint.h>

// Problem constants
#define BB   8
#define CQ   1024
#define CR   512
#define HID  256
#define NP   2304          // H*W = 48*48

#define KC   16            // k per smem stage
#define PS   20            // smem words per row: 8 hi-pair + 8 lo-pair + 4 pad

// ---------------------------------------------------------------------------
// Device-global scratch. "Planes" are fp16 hi/lo pairs packed in u32.
// ---------------------------------------------------------------------------
__device__ uint32_t g_qfT_hi[(size_t)BB * NP * CQ / 2];   // [b][i][c]
__device__ uint32_t g_qfT_lo[(size_t)BB * NP * CQ / 2];
__device__ uint32_t g_rfT_hi[(size_t)BB * NP * CR / 2];   // [b][p][c]
__device__ uint32_t g_rfT_lo[(size_t)BB * NP * CR / 2];
__device__ uint32_t g_rfS_hi[(size_t)BB * CR * NP / 2];   // [b][c][p]
__device__ uint32_t g_rfS_lo[(size_t)BB * CR * NP / 2];
__device__ uint32_t g_Wq_hi[(size_t)HID * CQ / 2];
__device__ uint32_t g_Wq_lo[(size_t)HID * CQ / 2];
__device__ uint32_t g_Wk_hi[(size_t)HID * CR / 2];
__device__ uint32_t g_Wk_lo[(size_t)HID * CR / 2];
__device__ uint32_t g_Q_hi[(size_t)BB * NP * HID / 2];    // [b][i][o]
__device__ uint32_t g_Q_lo[(size_t)BB * NP * HID / 2];
__device__ uint32_t g_K_hi[(size_t)BB * NP * HID / 2];    // [b][p][o]
__device__ uint32_t g_K_lo[(size_t)BB * NP * HID / 2];
__device__ float    g_attn[(size_t)BB * NP * NP];         // [b][i][p] fp32 logits
__device__ uint32_t g_at_hi[(size_t)BB * NP * NP / 2];    // [b][i][p] probs
__device__ uint32_t g_at_lo[(size_t)BB * NP * NP / 2];

// ---------------------------------------------------------------------------
// helpers
// ---------------------------------------------------------------------------
__device__ __forceinline__ void split_f16(float x, unsigned short &h, unsigned short &l) {
    __half hb = __float2half_rn(x);
    h = __half_as_ushort(hb);
    float r = x - __half2float(hb);
    l = __half_as_ushort(__float2half_rn(r));
}
__device__ __forceinline__ void split_pair_words(float x0, float x1,
                                                 uint32_t &hw, uint32_t &lw) {
    unsigned short h0, l0, h1, l1;
    split_f16(x0, h0, l0);
    split_f16(x1, h1, l1);
    hw = (uint32_t)h0 | ((uint32_t)h1 << 16);
    lw = (uint32_t)l0 | ((uint32_t)l1 << 16);
}

// fp16 inputs, fp32 accumulate
__device__ __forceinline__ void mma_f32acc(float c[4], const uint32_t a[4],
                                           const uint32_t b0, const uint32_t b1) {
    asm volatile(
        "mma.sync.aligned.m16n8k16.row.col.f32.f16.f16.f32 "
        "{%0,%1,%2,%3}, {%4,%5,%6,%7}, {%8,%9}, {%0,%1,%2,%3};\n"
        : "+f"(c[0]), "+f"(c[1]), "+f"(c[2]), "+f"(c[3])
        : "r"(a[0]), "r"(a[1]), "r"(a[2]), "r"(a[3]),
          "r"(b0), "r"(b1));
}
// fp16 inputs, fp16 accumulate (half2-packed c)
__device__ __forceinline__ void mma_f16acc(uint32_t c[2], const uint32_t a[4],
                                           const uint32_t b0, const uint32_t b1) {
    asm volatile(
        "mma.sync.aligned.m16n8k16.row.col.f16.f16.f16.f16 "
        "{%0,%1}, {%2,%3,%4,%5}, {%6,%7}, {%0,%1};\n"
        : "+r"(c[0]), "+r"(c[1])
        : "r"(a[0]), "r"(a[1]), "r"(a[2]), "r"(a[3]),
          "r"(b0), "r"(b1));
}

__device__ __forceinline__ void ldsm4(uint32_t r[4], uint32_t addr) {
    asm volatile("ldmatrix.sync.aligned.m8n8.x4.shared.b16 {%0,%1,%2,%3}, [%4];"
                 : "=r"(r[0]), "=r"(r[1]), "=r"(r[2]), "=r"(r[3]) : "r"(addr));
}
__device__ __forceinline__ void cpasync16(uint32_t saddr, const void* g) {
    asm volatile("cp.async.cg.shared.global [%0], [%1], 16;" :: "r"(saddr), "l"(g));
}
#define CP_COMMIT() asm volatile("cp.async.commit_group;" ::: "memory")
#define CP_WAIT0()  asm volatile("cp.async.wait_group 0;" ::: "memory")

// ---------------------------------------------------------------------------
// Elementwise split: fp32 -> hi/lo fp16 planes (pairs packed in u32).
// ---------------------------------------------------------------------------
__global__ void __launch_bounds__(256) split_pairs(
    const float* __restrict__ src,
    uint32_t* __restrict__ dhi, uint32_t* __restrict__ dlo, size_t npairs)
{
    size_t i = (size_t)blockIdx.x * 256 + threadIdx.x;
    if (i >= npairs) return;
    float x0 = src[2 * i], x1 = src[2 * i + 1];
    uint32_t hw, lw;
    split_pair_words(x0, x1, hw, lw);
    dhi[i] = hw;
    dlo[i] = lw;
}

// ---------------------------------------------------------------------------
// Tiled transpose + split: src fp32 [R][C] -> dst hi/lo fp16 [C][R].
// ---------------------------------------------------------------------------
__global__ void __launch_bounds__(256) transpose_split(
    const float* __restrict__ src,
    uint32_t* __restrict__ dhi, uint32_t* __restrict__ dlo,
    int R, int C)
{
    __shared__ float s[64][33];
    const int b = blockIdx.z;
    src += (size_t)b * R * C;
    const size_t dbatch = (size_t)C * (R >> 1);
    dhi += (size_t)b * dbatch;
    dlo += (size_t)b * dbatch;

    const int c0 = blockIdx.x * 32;
    const int r0 = blockIdx.y * 64;
    const int tx = threadIdx.x, ty = threadIdx.y;

    #pragma unroll
    for (int j = 0; j < 8; j++) {
        const int r = ty + 8 * j;
        s[r][tx] = src[(size_t)(r0 + r) * C + c0 + tx];
    }
    __syncthreads();

    #pragma unroll
    for (int j = 0; j < 4; j++) {
        const int cl = ty + 8 * j;
        const float x0 = s[2 * tx][cl];
        const float x1 = s[2 * tx + 1][cl];
        uint32_t hw, lw;
        split_pair_words(x0, x1, hw, lw);
        const size_t o = (size_t)(c0 + cl) * (R >> 1) + (r0 >> 1) + tx;
        dhi[o] = hw;
        dlo[o] = lw;
    }
}

// ---------------------------------------------------------------------------
// Split-fp16 tensor-core GEMM, cp.async double buffer + ldmatrix fragments.
//   C[m][n] = sum_k A[m][k] * B[n][k]  (both operands R-layout hi/lo planes)
// 128x128 CTA tile, 256 threads, 8 warps = 2(m) x 4(n), warp tile 64x32,
// m16n8k16 atoms. Per atom: ah*bh -> fp32 acc; ah*bl + al*bh -> fp16 acc
// (combined at epilogue). Cross terms are ~2^-11 of result, so fp16 acc
// noise lands at ~4e-6 relative — and fp16-acc HMMA may run at 2x rate.
// ---------------------------------------------------------------------------
template<bool BIAS, bool OSPLIT>
__global__ void __launch_bounds__(256) bgemm(
    const uint32_t* __restrict__ Ahi32, const uint32_t* __restrict__ Alo32,
    int lda, size_t sA,
    const uint32_t* __restrict__ Bhi32, const uint32_t* __restrict__ Blo32,
    int ldb, size_t sB,
    const float* __restrict__ bias,
    float* __restrict__ C, uint32_t* __restrict__ Chi, uint32_t* __restrict__ Clo,
    int ldc, size_t sC, int Ktot)
{
    __shared__ uint32_t As[2][128 * PS];
    __shared__ uint32_t Bs[2][128 * PS];

    const int bz = blockIdx.z;
    const __half* Ahi = (const __half*)Ahi32 + sA * bz;
    const __half* Alo = (const __half*)Alo32 + sA * bz;
    const __half* Bhi = (const __half*)Bhi32 + sB * bz;
    const __half* Blo = (const __half*)Blo32 + sB * bz;

    const int tid = threadIdx.x;
    const int m0  = blockIdx.x * 128;
    const int n0  = blockIdx.y * 128;

    // cp.async loader: thread -> (row, plane); copies 2x16B per operand/stage
    const int lrow = tid >> 1;
    const int lpl  = tid & 1;
    const __half* Asrc = (lpl ? Alo : Ahi) + (size_t)(m0 + lrow) * lda;
    const __half* Bsrc = (lpl ? Blo : Bhi) + (size_t)(n0 + lrow) * ldb;
    const uint32_t sdst = (uint32_t)(lrow * PS + lpl * 8) * 4;   // bytes in stage

    const uint32_t aS = (uint32_t)__cvta_generic_to_shared(&As[0][0]);
    const uint32_t bS = (uint32_t)__cvta_generic_to_shared(&Bs[0][0]);
    const uint32_t stageB = 128 * PS * 4;

    // warp/lane decomposition
    const int wid = tid >> 5, lane = tid & 31;
    const int wm = (wid & 1) * 64;
    const int wn = (wid >> 1) * 32;
    const int qr = lane >> 2, qc = lane & 3;

    // ldmatrix per-lane addresses (byte offsets within a stage)
    uint32_t aoff[4], boff[4];
    {
        const int arl = (lane & 7) + (lane & 8);
        const int awd = (lane & 16) ? 4 : 0;
        #pragma unroll
        for (int mt = 0; mt < 4; mt++)
            aoff[mt] = (uint32_t)(((wm + mt * 16 + arl) * PS + awd) * 4);
        const int brl = lane & 7;
        const int bwd = ((lane >> 3) & 3) * 4;
        #pragma unroll
        for (int nt = 0; nt < 4; nt++)
            boff[nt] = (uint32_t)(((wn + nt * 8 + brl) * PS + bwd) * 4);
    }

    float acc[4][4][4];
    uint32_t accx[4][4][2];                   // fp16x2 cross-term accumulators
    #pragma unroll
    for (int mt = 0; mt < 4; mt++)
        #pragma unroll
        for (int nt = 0; nt < 4; nt++) {
            #pragma unroll
            for (int r = 0; r < 4; r++) acc[mt][nt][r] = 0.f;
            accx[mt][nt][0] = 0u;
            accx[mt][nt][1] = 0u;
        }

    // ---- prologue: stage 0 ----
    cpasync16(aS + sdst,      Asrc);
    cpasync16(aS + sdst + 16, Asrc + 8);
    cpasync16(bS + sdst,      Bsrc);
    cpasync16(bS + sdst + 16, Bsrc + 8);
    CP_COMMIT();
    CP_WAIT0();
    __syncthreads();

    const int nk = Ktot / KC;
    int buf = 0;
    for (int kb = 0; kb < nk; kb++) {
        const bool has_next = (kb + 1) < nk;
        if (has_next) {
            const int k0 = (kb + 1) * KC;
            const uint32_t ad = aS + (buf ^ 1) * stageB + sdst;
            const uint32_t bd = bS + (buf ^ 1) * stageB + sdst;
            cpasync16(ad,      Asrc + k0);
            cpasync16(ad + 16, Asrc + k0 + 8);
            cpasync16(bd,      Bsrc + k0);
            cpasync16(bd + 16, Bsrc + k0 + 8);
            CP_COMMIT();
        }

        const uint32_t ab = aS + buf * stageB;
        const uint32_t bb = bS + buf * stageB;

        uint32_t ah[4][4], al[4][4];
        #pragma unroll
        for (int mt = 0; mt < 4; mt++) {
            ldsm4(ah[mt], ab + aoff[mt]);          // hi plane (words 0..7)
            ldsm4(al[mt], ab + aoff[mt] + 32);     // lo plane (words 8..15)
        }
        #pragma unroll
        for (int nt = 0; nt < 4; nt++) {
            uint32_t bv[4];                        // {b0h, b1h, b0l, b1l}
            ldsm4(bv, bb + boff[nt]);
            #pragma unroll
            for (int mt = 0; mt < 4; mt++)
                mma_f16acc(accx[mt][nt], ah[mt], bv[2], bv[3]);   // ah*bl (f16 acc)
            #pragma unroll
            for (int mt = 0; mt < 4; mt++)
                mma_f16acc(accx[mt][nt], al[mt], bv[0], bv[1]);   // al*bh (f16 acc)
            #pragma unroll
            for (int mt = 0; mt < 4; mt++)
                mma_f32acc(acc[mt][nt], ah[mt], bv[0], bv[1]);    // ah*bh (f32 acc)
        }

        if (has_next) {
            CP_WAIT0();
            __syncthreads();
            buf ^= 1;
        }
    }

    // ---- epilogue: combine f32 + f16 cross accumulators ----
    #pragma unroll
    for (int mt = 0; mt < 4; mt++) {
        #pragma unroll
        for (int nt = 0; nt < 4; nt++) {
            const int row = m0 + wm + mt * 16 + qr;
            const int col = n0 + wn + nt * 8 + 2 * qc;
            const float2 c01 = __half22float2(*(const __half2*)&accx[mt][nt][0]);
            const float2 c23 = __half22float2(*(const __half2*)&accx[mt][nt][1]);
            float v0 = acc[mt][nt][0] + c01.x, v1 = acc[mt][nt][1] + c01.y;
            float v2 = acc[mt][nt][2] + c23.x, v3 = acc[mt][nt][3] + c23.y;
            if (BIAS) {
                const float b0 = bias[col], b1 = bias[col + 1];
                v0 += b0; v1 += b1; v2 += b0; v3 += b1;
            }
            if (OSPLIT) {
                uint32_t* chb = Chi + (size_t)bz * (sC >> 1);
                uint32_t* clb = Clo + (size_t)bz * (sC >> 1);
                uint32_t hw, lw;
                split_pair_words(v0, v1, hw, lw);
                size_t o = (size_t)row * (ldc >> 1) + (col >> 1);
                chb[o] = hw; clb[o] = lw;
                split_pair_words(v2, v3, hw, lw);
                o = (size_t)(row + 8) * (ldc >> 1) + (col >> 1);
                chb[o] = hw; clb[o] = lw;
            } else {
                float* cb = C + sC * bz;
                *(float2*)&cb[(size_t)row * ldc + col]       = make_float2(v0, v1);
                *(float2*)&cb[(size_t)(row + 8) * ldc + col] = make_float2(v2, v3);
            }
        }
    }
}

// ---------------------------------------------------------------------------
// Fused row softmax + fp16 split: S[b][i][p] fp32 -> prob planes [b][i][p].
// One CTA per row (2304 elements cached in smem), 256 threads.
// ---------------------------------------------------------------------------
__global__ void __launch_bounds__(256) softmax_split(
    const float* __restrict__ S,
    uint32_t* __restrict__ ph_out, uint32_t* __restrict__ pl_out)
{
    __shared__ float row[NP];
    __shared__ float red[9];
    const int b = blockIdx.y, i = blockIdx.x, t = threadIdx.x;
    const int wid = t >> 5, lane = t & 31;
    const float* src = S + ((size_t)b * NP + i) * NP;

    float lm = -3.402823466e38f;
    #pragma unroll
    for (int j = 0; j < 9; j++) {
        const int idx = j * 256 + t;
        const float x = src[idx];
        row[idx] = x;
        lm = fmaxf(lm, x);
    }
    #pragma unroll
    for (int o = 16; o; o >>= 1) lm = fmaxf(lm, __shfl_xor_sync(0xffffffffu, lm, o));
    if (lane == 0) red[wid] = lm;
    __syncthreads();
    if (t == 0) {
        float M = red[0];
        #pragma unroll
        for (int k = 1; k < 8; k++) M = fmaxf(M, red[k]);
        red[8] = M;
    }
    __syncthreads();
    const float M = red[8];

    float ls = 0.f;
    #pragma unroll
    for (int j = 0; j < 9; j++) {
        const int idx = j * 256 + t;
        const float e = __expf(row[idx] - M);
        row[idx] = e;
        ls += e;
    }
    #pragma unroll
    for (int o = 16; o; o >>= 1) ls += __shfl_xor_sync(0xffffffffu, ls, o);
    if (lane == 0) red[wid] = ls;
    __syncthreads();
    if (t == 0) {
        float s2 = 0.f;
        #pragma unroll
        for (int k = 0; k < 8; k++) s2 += red[k];
        red[8] = 1.0f / s2;
    }
    __syncthreads();
    const float inv = red[8];

    uint32_t* oh = ph_out + ((size_t)b * NP + i) * (NP / 2);
    uint32_t* ol = pl_out + ((size_t)b * NP + i) * (NP / 2);
    #pragma unroll
    for (int j = 0; j < 5; j++) {
        const int q = j * 256 + t;
        if (q < NP / 2) {
            const float2 xv = *(const float2*)&row[2 * q];
            uint32_t hw, lw;
            split_pair_words(xv.x * inv, xv.y * inv, hw, lw);
            oh[q] = hw;
            ol[q] = lw;
        }
    }
}

// ---------------------------------------------------------------------------
extern "C" void kernel_launch(void* const* d_in, const int* in_sizes, int n_in,
                              void* d_out, int out_size)
{
    const float* qf = (const float*)d_in[0];   // [B, CQ, 48, 48]
    const float* rf = (const float*)d_in[1];   // [B, CR, 48, 48]
    const float* Wq = (const float*)d_in[2];   // [HID, CQ]
    const float* bq = (const float*)d_in[3];   // [HID]
    const float* Wk = (const float*)d_in[4];   // [HID, CR]
    const float* bk = (const float*)d_in[5];   // [HID]
    float* out = (float*)d_out;                // [B, CR, 48, 48]

    uint32_t *qfTh, *qfTl, *rfTh, *rfTl, *rfSh, *rfSl;
    uint32_t *Wqh, *Wql, *Wkh, *Wkl, *Qh, *Ql, *Kh, *Kl, *ath, *atl;
    float *Ap;
    cudaGetSymbolAddress((void**)&qfTh, g_qfT_hi);
    cudaGetSymbolAddress((void**)&qfTl, g_qfT_lo);
    cudaGetSymbolAddress((void**)&rfTh, g_rfT_hi);
    cudaGetSymbolAddress((void**)&rfTl, g_rfT_lo);
    cudaGetSymbolAddress((void**)&rfSh, g_rfS_hi);
    cudaGetSymbolAddress((void**)&rfSl, g_rfS_lo);
    cudaGetSymbolAddress((void**)&Wqh, g_Wq_hi);
    cudaGetSymbolAddress((void**)&Wql, g_Wq_lo);
    cudaGetSymbolAddress((void**)&Wkh, g_Wk_hi);
    cudaGetSymbolAddress((void**)&Wkl, g_Wk_lo);
    cudaGetSymbolAddress((void**)&Qh, g_Q_hi);
    cudaGetSymbolAddress((void**)&Ql, g_Q_lo);
    cudaGetSymbolAddress((void**)&Kh, g_K_hi);
    cudaGetSymbolAddress((void**)&Kl, g_K_lo);
    cudaGetSymbolAddress((void**)&ath, g_at_hi);
    cudaGetSymbolAddress((void**)&atl, g_at_lo);
    cudaGetSymbolAddress((void**)&Ap, g_attn);

    // ---- prepass: splits + transposes ----
    {
        size_t np;
        np = (size_t)HID * CQ / 2;
        split_pairs<<<(unsigned)((np + 255) / 256), 256>>>(Wq, Wqh, Wql, np);
        np = (size_t)HID * CR / 2;
        split_pairs<<<(unsigned)((np + 255) / 256), 256>>>(Wk, Wkh, Wkl, np);
        np = (size_t)BB * CR * NP / 2;
        split_pairs<<<(unsigned)((np + 255) / 256), 256>>>(rf, rfSh, rfSl, np);
    }
    transpose_split<<<dim3(NP / 32, CQ / 64, BB), dim3(32, 8)>>>(qf, qfTh, qfTl, CQ, NP);
    transpose_split<<<dim3(NP / 32, CR / 64, BB), dim3(32, 8)>>>(rf, rfTh, rfTl, CR, NP);

    // ---- GEMM1: Q[i][o] = qfT[i][c] * Wq[o][c] + bq -> hi/lo planes ----
    bgemm<true, true><<<dim3(NP / 128, HID / 128, BB), 256>>>(
        qfTh, qfTl, CQ, (size_t)NP * CQ,
        Wqh, Wql, CQ, 0,
        bq,
        nullptr, Qh, Ql, HID, (size_t)NP * HID,
        CQ);

    // ---- GEMM2: K[p][o] = rfT[p][c] * Wk[o][c] + bk -> hi/lo planes ----
    bgemm<true, true><<<dim3(NP / 128, HID / 128, BB), 256>>>(
        rfTh, rfTl, CR, (size_t)NP * CR,
        Wkh, Wkl, CR, 0,
        bk,
        nullptr, Kh, Kl, HID, (size_t)NP * HID,
        CR);

    // ---- GEMM3: S[i][p] = Q[i][k] * K[p][k]  (fp32 out) ----
    bgemm<false, false><<<dim3(NP / 128, NP / 128, BB), 256>>>(
        Qh, Ql, HID, (size_t)NP * HID,
        Kh, Kl, HID, (size_t)NP * HID,
        nullptr,
        Ap, nullptr, nullptr, NP, (size_t)NP * NP,
        HID);

    // ---- fused softmax over p + fp16 split to prob planes [i][p] ----
    softmax_split<<<dim3(NP, BB), 256>>>(Ap, ath, atl);

    // ---- GEMM4: out[c][i] = rfS[c][p] * attn[i][p]  (fp32 out) ----
    bgemm<false, false><<<dim3(CR / 128, NP / 128, BB), 256>>>(
        rfSh, rfSl, NP, (size_t)CR * NP,
        ath, atl, NP, (size_t)NP * NP,
        nullptr,
        out, nullptr, nullptr, NP, (size_t)CR * NP,
        NP);
}

// round 10
// speedup vs baseline: 1.4054x; 1.4054x over previous
#include <cuda_runtime.h>
#include <cuda_fp16.h>
#include <math.h>
#include <stdint.h>

// Problem constants
#define BB   8
#define CQ   1024
#define CR   512
#define HID  256
#define NP   2304          // H*W = 48*48

#define KC   16            // k per smem stage
#define PS   20            // smem words per row: 8 hi-pair + 8 lo-pair + 4 pad

// ---------------------------------------------------------------------------
// Device-global scratch. "Planes" are fp16 hi/lo pairs packed in u32.
// ---------------------------------------------------------------------------
__device__ uint32_t g_qfT_hi[(size_t)BB * NP * CQ / 2];   // [b][i][c]
__device__ uint32_t g_qfT_lo[(size_t)BB * NP * CQ / 2];
__device__ uint32_t g_rfT_hi[(size_t)BB * NP * CR / 2];   // [b][p][c]
__device__ uint32_t g_rfT_lo[(size_t)BB * NP * CR / 2];
__device__ uint32_t g_rfS_hi[(size_t)BB * CR * NP / 2];   // [b][c][p]
__device__ uint32_t g_rfS_lo[(size_t)BB * CR * NP / 2];
__device__ uint32_t g_Wq_hi[(size_t)HID * CQ / 2];
__device__ uint32_t g_Wq_lo[(size_t)HID * CQ / 2];
__device__ uint32_t g_Wk_hi[(size_t)HID * CR / 2];
__device__ uint32_t g_Wk_lo[(size_t)HID * CR / 2];
__device__ uint32_t g_Q_hi[(size_t)BB * NP * HID / 2];    // [b][i][o]
__device__ uint32_t g_Q_lo[(size_t)BB * NP * HID / 2];
__device__ uint32_t g_K_hi[(size_t)BB * NP * HID / 2];    // [b][p][o]
__device__ uint32_t g_K_lo[(size_t)BB * NP * HID / 2];
__device__ float    g_attn[(size_t)BB * NP * NP];         // [b][i][p] fp32 logits
__device__ uint32_t g_at_hi[(size_t)BB * NP * NP / 2];    // [b][i][p] probs (fp16, single plane)

// ---------------------------------------------------------------------------
// helpers
// ---------------------------------------------------------------------------
__device__ __forceinline__ void split_f16(float x, unsigned short &h, unsigned short &l) {
    __half hb = __float2half_rn(x);
    h = __half_as_ushort(hb);
    float r = x - __half2float(hb);
    l = __half_as_ushort(__float2half_rn(r));
}
__device__ __forceinline__ void split_pair_words(float x0, float x1,
                                                 uint32_t &hw, uint32_t &lw) {
    unsigned short h0, l0, h1, l1;
    split_f16(x0, h0, l0);
    split_f16(x1, h1, l1);
    hw = (uint32_t)h0 | ((uint32_t)h1 << 16);
    lw = (uint32_t)l0 | ((uint32_t)l1 << 16);
}

// fp16 inputs, fp32 accumulate
__device__ __forceinline__ void mma_f16(float c[4], const uint32_t a[4],
                                        const uint32_t b0, const uint32_t b1) {
    asm volatile(
        "mma.sync.aligned.m16n8k16.row.col.f32.f16.f16.f32 "
        "{%0,%1,%2,%3}, {%4,%5,%6,%7}, {%8,%9}, {%0,%1,%2,%3};\n"
        : "+f"(c[0]), "+f"(c[1]), "+f"(c[2]), "+f"(c[3])
        : "r"(a[0]), "r"(a[1]), "r"(a[2]), "r"(a[3]),
          "r"(b0), "r"(b1));
}

__device__ __forceinline__ void ldsm4(uint32_t r[4], uint32_t addr) {
    asm volatile("ldmatrix.sync.aligned.m8n8.x4.shared.b16 {%0,%1,%2,%3}, [%4];"
                 : "=r"(r[0]), "=r"(r[1]), "=r"(r[2]), "=r"(r[3]) : "r"(addr));
}
__device__ __forceinline__ void ldsm2(uint32_t r[2], uint32_t addr) {
    asm volatile("ldmatrix.sync.aligned.m8n8.x2.shared.b16 {%0,%1}, [%2];"
                 : "=r"(r[0]), "=r"(r[1]) : "r"(addr));
}
__device__ __forceinline__ void cpasync16(uint32_t saddr, const void* g) {
    asm volatile("cp.async.cg.shared.global [%0], [%1], 16;" :: "r"(saddr), "l"(g));
}
#define CP_COMMIT() asm volatile("cp.async.commit_group;" ::: "memory")
#define CP_WAIT0()  asm volatile("cp.async.wait_group 0;" ::: "memory")

// ---------------------------------------------------------------------------
// Elementwise split: fp32 -> hi/lo fp16 planes (pairs packed in u32).
// ---------------------------------------------------------------------------
__global__ void __launch_bounds__(256) split_pairs(
    const float* __restrict__ src,
    uint32_t* __restrict__ dhi, uint32_t* __restrict__ dlo, size_t npairs)
{
    size_t i = (size_t)blockIdx.x * 256 + threadIdx.x;
    if (i >= npairs) return;
    float x0 = src[2 * i], x1 = src[2 * i + 1];
    uint32_t hw, lw;
    split_pair_words(x0, x1, hw, lw);
    dhi[i] = hw;
    dlo[i] = lw;
}

// ---------------------------------------------------------------------------
// Tiled transpose + split: src fp32 [R][C] -> dst hi/lo fp16 [C][R].
// ---------------------------------------------------------------------------
__global__ void __launch_bounds__(256) transpose_split(
    const float* __restrict__ src,
    uint32_t* __restrict__ dhi, uint32_t* __restrict__ dlo,
    int R, int C)
{
    __shared__ float s[64][33];
    const int b = blockIdx.z;
    src += (size_t)b * R * C;
    const size_t dbatch = (size_t)C * (R >> 1);
    dhi += (size_t)b * dbatch;
    dlo += (size_t)b * dbatch;

    const int c0 = blockIdx.x * 32;
    const int r0 = blockIdx.y * 64;
    const int tx = threadIdx.x, ty = threadIdx.y;

    #pragma unroll
    for (int j = 0; j < 8; j++) {
        const int r = ty + 8 * j;
        s[r][tx] = src[(size_t)(r0 + r) * C + c0 + tx];
    }
    __syncthreads();

    #pragma unroll
    for (int j = 0; j < 4; j++) {
        const int cl = ty + 8 * j;
        const float x0 = s[2 * tx][cl];
        const float x1 = s[2 * tx + 1][cl];
        uint32_t hw, lw;
        split_pair_words(x0, x1, hw, lw);
        const size_t o = (size_t)(c0 + cl) * (R >> 1) + (r0 >> 1) + tx;
        dhi[o] = hw;
        dlo[o] = lw;
    }
}

// ---------------------------------------------------------------------------
// Split-fp16 tensor-core GEMM, cp.async double buffer + ldmatrix fragments.
//   C[m][n] = sum_k A[m][k] * B[n][k]  (R-layout planes)
// 128x128 CTA tile, 256 threads, 8 warps = 2(m) x 4(n), warp tile 64x32,
// m16n8k16 atoms, fp32 accumulate only.
// BSINGLE=false: A and B both hi/lo split; 3 MMAs/atom (ah*bh + ah*bl + al*bh).
// BSINGLE=true : B is a single fp16 plane; 2 MMAs/atom (ah*b + al*b).
// ---------------------------------------------------------------------------
template<bool BIAS, bool OSPLIT, bool BSINGLE>
__global__ void __launch_bounds__(256, 2) bgemm(
    const uint32_t* __restrict__ Ahi32, const uint32_t* __restrict__ Alo32,
    int lda, size_t sA,
    const uint32_t* __restrict__ Bhi32, const uint32_t* __restrict__ Blo32,
    int ldb, size_t sB,
    const float* __restrict__ bias,
    float* __restrict__ C, uint32_t* __restrict__ Chi, uint32_t* __restrict__ Clo,
    int ldc, size_t sC, int Ktot)
{
    __shared__ uint32_t As[2][128 * PS];
    __shared__ uint32_t Bs[2][128 * PS];

    const int bz = blockIdx.z;
    const __half* Ahi = (const __half*)Ahi32 + sA * bz;
    const __half* Alo = (const __half*)Alo32 + sA * bz;
    const __half* Bhi = (const __half*)Bhi32 + sB * bz;
    const __half* Blo = (const __half*)Blo32 + sB * bz;

    const int tid = threadIdx.x;
    const int m0  = blockIdx.x * 128;
    const int n0  = blockIdx.y * 128;

    // cp.async loader: thread -> (row, plane); copies 2x16B per operand/stage
    const int lrow = tid >> 1;
    const int lpl  = tid & 1;
    const __half* Asrc = (lpl ? Alo : Ahi) + (size_t)(m0 + lrow) * lda;
    const __half* Bsrc = ((lpl && !BSINGLE) ? Blo : Bhi) + (size_t)(n0 + lrow) * ldb;
    const bool   bload = (!BSINGLE) || (lpl == 0);
    const uint32_t sdst = (uint32_t)(lrow * PS + lpl * 8) * 4;   // bytes in stage

    const uint32_t aS = (uint32_t)__cvta_generic_to_shared(&As[0][0]);
    const uint32_t bS = (uint32_t)__cvta_generic_to_shared(&Bs[0][0]);
    const uint32_t stageB = 128 * PS * 4;

    // warp/lane decomposition
    const int wid = tid >> 5, lane = tid & 31;
    const int wm = (wid & 1) * 64;
    const int wn = (wid >> 1) * 32;
    const int qr = lane >> 2, qc = lane & 3;

    // ldmatrix per-lane addresses (byte offsets within a stage)
    uint32_t aoff[4], boff[4];
    {
        const int arl = (lane & 7) + (lane & 8);
        const int awd = (lane & 16) ? 4 : 0;
        #pragma unroll
        for (int mt = 0; mt < 4; mt++)
            aoff[mt] = (uint32_t)(((wm + mt * 16 + arl) * PS + awd) * 4);
        const int brl = lane & 7;
        const int bwd = BSINGLE ? (((lane >> 3) & 1) * 4)     // x2: 2 matrices
                                : (((lane >> 3) & 3) * 4);    // x4: 4 matrices
        #pragma unroll
        for (int nt = 0; nt < 4; nt++)
            boff[nt] = (uint32_t)(((wn + nt * 8 + brl) * PS + bwd) * 4);
    }

    float acc[4][4][4];
    #pragma unroll
    for (int mt = 0; mt < 4; mt++)
        #pragma unroll
        for (int nt = 0; nt < 4; nt++)
            #pragma unroll
            for (int r = 0; r < 4; r++) acc[mt][nt][r] = 0.f;

    // ---- prologue: stage 0 ----
    cpasync16(aS + sdst,      Asrc);
    cpasync16(aS + sdst + 16, Asrc + 8);
    if (bload) {
        cpasync16(bS + sdst,      Bsrc);
        cpasync16(bS + sdst + 16, Bsrc + 8);
    }
    CP_COMMIT();
    CP_WAIT0();
    __syncthreads();

    const int nk = Ktot / KC;
    int buf = 0;
    for (int kb = 0; kb < nk; kb++) {
        const bool has_next = (kb + 1) < nk;
        if (has_next) {
            const int k0 = (kb + 1) * KC;
            const uint32_t ad = aS + (buf ^ 1) * stageB + sdst;
            cpasync16(ad,      Asrc + k0);
            cpasync16(ad + 16, Asrc + k0 + 8);
            if (bload) {
                const uint32_t bd = bS + (buf ^ 1) * stageB + sdst;
                cpasync16(bd,      Bsrc + k0);
                cpasync16(bd + 16, Bsrc + k0 + 8);
            }
            CP_COMMIT();
        }

        const uint32_t ab = aS + buf * stageB;
        const uint32_t bb = bS + buf * stageB;

        uint32_t ah[4][4], al[4][4];
        #pragma unroll
        for (int mt = 0; mt < 4; mt++) {
            ldsm4(ah[mt], ab + aoff[mt]);          // hi plane (words 0..7)
            ldsm4(al[mt], ab + aoff[mt] + 32);     // lo plane (words 8..15)
        }
        #pragma unroll
        for (int nt = 0; nt < 4; nt++) {
            if (BSINGLE) {
                uint32_t bv[2];                    // {b0, b1} single plane
                ldsm2(bv, bb + boff[nt]);
                #pragma unroll
                for (int mt = 0; mt < 4; mt++)
                    mma_f16(acc[mt][nt], ah[mt], bv[0], bv[1]);   // vh*p
                #pragma unroll
                for (int mt = 0; mt < 4; mt++)
                    mma_f16(acc[mt][nt], al[mt], bv[0], bv[1]);   // vl*p
            } else {
                uint32_t bv[4];                    // {b0h, b1h, b0l, b1l}
                ldsm4(bv, bb + boff[nt]);
                // term-major: each acc[mt][nt] reused at distance 4
                #pragma unroll
                for (int mt = 0; mt < 4; mt++)
                    mma_f16(acc[mt][nt], ah[mt], bv[2], bv[3]);   // ah*bl
                #pragma unroll
                for (int mt = 0; mt < 4; mt++)
                    mma_f16(acc[mt][nt], al[mt], bv[0], bv[1]);   // al*bh
                #pragma unroll
                for (int mt = 0; mt < 4; mt++)
                    mma_f16(acc[mt][nt], ah[mt], bv[0], bv[1]);   // ah*bh
            }
        }

        if (has_next) {
            CP_WAIT0();
            __syncthreads();
            buf ^= 1;
        }
    }

    // ---- epilogue ----
    #pragma unroll
    for (int mt = 0; mt < 4; mt++) {
        #pragma unroll
        for (int nt = 0; nt < 4; nt++) {
            const int row = m0 + wm + mt * 16 + qr;
            const int col = n0 + wn + nt * 8 + 2 * qc;
            float v0 = acc[mt][nt][0], v1 = acc[mt][nt][1];
            float v2 = acc[mt][nt][2], v3 = acc[mt][nt][3];
            if (BIAS) {
                const float b0 = bias[col], b1 = bias[col + 1];
                v0 += b0; v1 += b1; v2 += b0; v3 += b1;
            }
            if (OSPLIT) {
                uint32_t* chb = Chi + (size_t)bz * (sC >> 1);
                uint32_t* clb = Clo + (size_t)bz * (sC >> 1);
                uint32_t hw, lw;
                split_pair_words(v0, v1, hw, lw);
                size_t o = (size_t)row * (ldc >> 1) + (col >> 1);
                chb[o] = hw; clb[o] = lw;
                split_pair_words(v2, v3, hw, lw);
                o = (size_t)(row + 8) * (ldc >> 1) + (col >> 1);
                chb[o] = hw; clb[o] = lw;
            } else {
                float* cb = C + sC * bz;
                *(float2*)&cb[(size_t)row * ldc + col]       = make_float2(v0, v1);
                *(float2*)&cb[(size_t)(row + 8) * ldc + col] = make_float2(v2, v3);
            }
        }
    }
}

// ---------------------------------------------------------------------------
// Fused row softmax + fp16 quantize: S[b][i][p] fp32 -> single prob plane.
// One CTA per row (2304 elements cached in smem), 256 threads.
// ---------------------------------------------------------------------------
__global__ void __launch_bounds__(256) softmax_split(
    const float* __restrict__ S,
    uint32_t* __restrict__ ph_out)
{
    __shared__ float row[NP];
    __shared__ float red[9];
    const int b = blockIdx.y, i = blockIdx.x, t = threadIdx.x;
    const int wid = t >> 5, lane = t & 31;
    const float* src = S + ((size_t)b * NP + i) * NP;

    float lm = -3.402823466e38f;
    #pragma unroll
    for (int j = 0; j < 9; j++) {
        const int idx = j * 256 + t;
        const float x = src[idx];
        row[idx] = x;
        lm = fmaxf(lm, x);
    }
    #pragma unroll
    for (int o = 16; o; o >>= 1) lm = fmaxf(lm, __shfl_xor_sync(0xffffffffu, lm, o));
    if (lane == 0) red[wid] = lm;
    __syncthreads();
    if (t == 0) {
        float M = red[0];
        #pragma unroll
        for (int k = 1; k < 8; k++) M = fmaxf(M, red[k]);
        red[8] = M;
    }
    __syncthreads();
    const float M = red[8];

    float ls = 0.f;
    #pragma unroll
    for (int j = 0; j < 9; j++) {
        const int idx = j * 256 + t;
        const float e = __expf(row[idx] - M);
        row[idx] = e;
        ls += e;
    }
    #pragma unroll
    for (int o = 16; o; o >>= 1) ls += __shfl_xor_sync(0xffffffffu, ls, o);
    if (lane == 0) red[wid] = ls;
    __syncthreads();
    if (t == 0) {
        float s2 = 0.f;
        #pragma unroll
        for (int k = 0; k < 8; k++) s2 += red[k];
        red[8] = 1.0f / s2;
    }
    __syncthreads();
    const float inv = red[8];

    uint32_t* oh = ph_out + ((size_t)b * NP + i) * (NP / 2);
    #pragma unroll
    for (int j = 0; j < 5; j++) {
        const int q = j * 256 + t;
        if (q < NP / 2) {
            const float2 xv = *(const float2*)&row[2 * q];
            const __half2 h2 = __floats2half2_rn(xv.x * inv, xv.y * inv);
            oh[q] = *(const uint32_t*)&h2;
        }
    }
}

// ---------------------------------------------------------------------------
extern "C" void kernel_launch(void* const* d_in, const int* in_sizes, int n_in,
                              void* d_out, int out_size)
{
    const float* qf = (const float*)d_in[0];   // [B, CQ, 48, 48]
    const float* rf = (const float*)d_in[1];   // [B, CR, 48, 48]
    const float* Wq = (const float*)d_in[2];   // [HID, CQ]
    const float* bq = (const float*)d_in[3];   // [HID]
    const float* Wk = (const float*)d_in[4];   // [HID, CR]
    const float* bk = (const float*)d_in[5];   // [HID]
    float* out = (float*)d_out;                // [B, CR, 48, 48]

    uint32_t *qfTh, *qfTl, *rfTh, *rfTl, *rfSh, *rfSl;
    uint32_t *Wqh, *Wql, *Wkh, *Wkl, *Qh, *Ql, *Kh, *Kl, *ath;
    float *Ap;
    cudaGetSymbolAddress((void**)&qfTh, g_qfT_hi);
    cudaGetSymbolAddress((void**)&qfTl, g_qfT_lo);
    cudaGetSymbolAddress((void**)&rfTh, g_rfT_hi);
    cudaGetSymbolAddress((void**)&rfTl, g_rfT_lo);
    cudaGetSymbolAddress((void**)&rfSh, g_rfS_hi);
    cudaGetSymbolAddress((void**)&rfSl, g_rfS_lo);
    cudaGetSymbolAddress((void**)&Wqh, g_Wq_hi);
    cudaGetSymbolAddress((void**)&Wql, g_Wq_lo);
    cudaGetSymbolAddress((void**)&Wkh, g_Wk_hi);
    cudaGetSymbolAddress((void**)&Wkl, g_Wk_lo);
    cudaGetSymbolAddress((void**)&Qh, g_Q_hi);
    cudaGetSymbolAddress((void**)&Ql, g_Q_lo);
    cudaGetSymbolAddress((void**)&Kh, g_K_hi);
    cudaGetSymbolAddress((void**)&Kl, g_K_lo);
    cudaGetSymbolAddress((void**)&ath, g_at_hi);
    cudaGetSymbolAddress((void**)&Ap, g_attn);

    // ---- prepass: splits + transposes ----
    {
        size_t np;
        np = (size_t)HID * CQ / 2;
        split_pairs<<<(unsigned)((np + 255) / 256), 256>>>(Wq, Wqh, Wql, np);
        np = (size_t)HID * CR / 2;
        split_pairs<<<(unsigned)((np + 255) / 256), 256>>>(Wk, Wkh, Wkl, np);
        np = (size_t)BB * CR * NP / 2;
        split_pairs<<<(unsigned)((np + 255) / 256), 256>>>(rf, rfSh, rfSl, np);
    }
    transpose_split<<<dim3(NP / 32, CQ / 64, BB), dim3(32, 8)>>>(qf, qfTh, qfTl, CQ, NP);
    transpose_split<<<dim3(NP / 32, CR / 64, BB), dim3(32, 8)>>>(rf, rfTh, rfTl, CR, NP);

    // ---- GEMM1: Q[i][o] = qfT[i][c] * Wq[o][c] + bq -> hi/lo planes ----
    bgemm<true, true, false><<<dim3(NP / 128, HID / 128, BB), 256>>>(
        qfTh, qfTl, CQ, (size_t)NP * CQ,
        Wqh, Wql, CQ, 0,
        bq,
        nullptr, Qh, Ql, HID, (size_t)NP * HID,
        CQ);

    // ---- GEMM2: K[p][o] = rfT[p][c] * Wk[o][c] + bk -> hi/lo planes ----
    bgemm<true, true, false><<<dim3(NP / 128, HID / 128, BB), 256>>>(
        rfTh, rfTl, CR, (size_t)NP * CR,
        Wkh, Wkl, CR, 0,
        bk,
        nullptr, Kh, Kl, HID, (size_t)NP * HID,
        CR);

    // ---- GEMM3: S[i][p] = Q[i][k] * K[p][k]  (fp32 out) ----
    bgemm<false, false, false><<<dim3(NP / 128, NP / 128, BB), 256>>>(
        Qh, Ql, HID, (size_t)NP * HID,
        Kh, Kl, HID, (size_t)NP * HID,
        nullptr,
        Ap, nullptr, nullptr, NP, (size_t)NP * NP,
        HID);

    // ---- fused softmax over p -> single fp16 prob plane [i][p] ----
    softmax_split<<<dim3(NP, BB), 256>>>(Ap, ath);

    // ---- GEMM4: out[c][i] = rfS[c][p] * attn[i][p]; B single plane, 2 MMAs ----
    bgemm<false, false, true><<<dim3(CR / 128, NP / 128, BB), 256>>>(
        rfSh, rfSl, NP, (size_t)CR * NP,
        ath, ath, NP, (size_t)NP * NP,
        nullptr,
        out, nullptr, nullptr, NP, (size_t)CR * NP,
        NP);
}

// round 11
// speedup vs baseline: 1.6079x; 1.1441x over previous
#include <cuda_runtime.h>
#include <cuda_fp16.h>
#include <math.h>
#include <stdint.h>

// Problem constants
#define BB   8
#define CQ   1024
#define CR   512
#define HID  256
#define NP   2304          // H*W = 48*48

#define KC   16            // k per smem stage
#define PS   20            // smem words per row: 8 hi-pair + 8 lo-pair + 4 pad

// ---------------------------------------------------------------------------
// Device-global scratch. "Planes" are fp16 hi/lo pairs packed in u32.
// ---------------------------------------------------------------------------
__device__ uint32_t g_qfT_hi[(size_t)BB * NP * CQ / 2];   // [b][i][c]
__device__ uint32_t g_qfT_lo[(size_t)BB * NP * CQ / 2];
__device__ uint32_t g_rfT_hi[(size_t)BB * NP * CR / 2];   // [b][p][c]
__device__ uint32_t g_rfT_lo[(size_t)BB * NP * CR / 2];
__device__ uint32_t g_rfS[(size_t)BB * CR * NP / 2];      // [b][c][p] V, single fp16
__device__ uint32_t g_Wq_hi[(size_t)HID * CQ / 2];
__device__ uint32_t g_Wq_lo[(size_t)HID * CQ / 2];
__device__ uint32_t g_Wk_hi[(size_t)HID * CR / 2];
__device__ uint32_t g_Wk_lo[(size_t)HID * CR / 2];
__device__ uint32_t g_Q_hi[(size_t)BB * NP * HID / 2];    // [b][i][o]
__device__ uint32_t g_Q_lo[(size_t)BB * NP * HID / 2];
__device__ uint32_t g_K_hi[(size_t)BB * NP * HID / 2];    // [b][p][o]
__device__ uint32_t g_K_lo[(size_t)BB * NP * HID / 2];
__device__ float    g_attn[(size_t)BB * NP * NP];         // [b][i][p] fp32 logits
__device__ uint32_t g_at[(size_t)BB * NP * NP / 2];       // [b][i][p] probs, single fp16

// ---------------------------------------------------------------------------
// helpers
// ---------------------------------------------------------------------------
__device__ __forceinline__ void split_f16(float x, unsigned short &h, unsigned short &l) {
    __half hb = __float2half_rn(x);
    h = __half_as_ushort(hb);
    float r = x - __half2float(hb);
    l = __half_as_ushort(__float2half_rn(r));
}
__device__ __forceinline__ void split_pair_words(float x0, float x1,
                                                 uint32_t &hw, uint32_t &lw) {
    unsigned short h0, l0, h1, l1;
    split_f16(x0, h0, l0);
    split_f16(x1, h1, l1);
    hw = (uint32_t)h0 | ((uint32_t)h1 << 16);
    lw = (uint32_t)l0 | ((uint32_t)l1 << 16);
}

// fp16 inputs, fp32 accumulate
__device__ __forceinline__ void mma_f16(float c[4], const uint32_t a[4],
                                        const uint32_t b0, const uint32_t b1) {
    asm volatile(
        "mma.sync.aligned.m16n8k16.row.col.f32.f16.f16.f32 "
        "{%0,%1,%2,%3}, {%4,%5,%6,%7}, {%8,%9}, {%0,%1,%2,%3};\n"
        : "+f"(c[0]), "+f"(c[1]), "+f"(c[2]), "+f"(c[3])
        : "r"(a[0]), "r"(a[1]), "r"(a[2]), "r"(a[3]),
          "r"(b0), "r"(b1));
}

__device__ __forceinline__ void ldsm4(uint32_t r[4], uint32_t addr) {
    asm volatile("ldmatrix.sync.aligned.m8n8.x4.shared.b16 {%0,%1,%2,%3}, [%4];"
                 : "=r"(r[0]), "=r"(r[1]), "=r"(r[2]), "=r"(r[3]) : "r"(addr));
}
__device__ __forceinline__ void ldsm2(uint32_t r[2], uint32_t addr) {
    asm volatile("ldmatrix.sync.aligned.m8n8.x2.shared.b16 {%0,%1}, [%2];"
                 : "=r"(r[0]), "=r"(r[1]) : "r"(addr));
}
__device__ __forceinline__ void cpasync16(uint32_t saddr, const void* g) {
    asm volatile("cp.async.cg.shared.global [%0], [%1], 16;" :: "r"(saddr), "l"(g));
}
#define CP_COMMIT() asm volatile("cp.async.commit_group;" ::: "memory")
#define CP_WAIT0()  asm volatile("cp.async.wait_group 0;" ::: "memory")

// ---------------------------------------------------------------------------
// Elementwise split: fp32 -> hi/lo fp16 planes (pairs packed in u32).
// ---------------------------------------------------------------------------
__global__ void __launch_bounds__(256) split_pairs(
    const float* __restrict__ src,
    uint32_t* __restrict__ dhi, uint32_t* __restrict__ dlo, size_t npairs)
{
    size_t i = (size_t)blockIdx.x * 256 + threadIdx.x;
    if (i >= npairs) return;
    float x0 = src[2 * i], x1 = src[2 * i + 1];
    uint32_t hw, lw;
    split_pair_words(x0, x1, hw, lw);
    dhi[i] = hw;
    dlo[i] = lw;
}

// ---------------------------------------------------------------------------
// Elementwise convert: fp32 -> single fp16 plane (pairs packed in u32).
// ---------------------------------------------------------------------------
__global__ void __launch_bounds__(256) cvt_pairs(
    const float* __restrict__ src,
    uint32_t* __restrict__ dst, size_t npairs)
{
    size_t i = (size_t)blockIdx.x * 256 + threadIdx.x;
    if (i >= npairs) return;
    const __half2 h2 = __floats2half2_rn(src[2 * i], src[2 * i + 1]);
    dst[i] = *(const uint32_t*)&h2;
}

// ---------------------------------------------------------------------------
// Tiled transpose + split: src fp32 [R][C] -> dst hi/lo fp16 [C][R].
// ---------------------------------------------------------------------------
__global__ void __launch_bounds__(256) transpose_split(
    const float* __restrict__ src,
    uint32_t* __restrict__ dhi, uint32_t* __restrict__ dlo,
    int R, int C)
{
    __shared__ float s[64][33];
    const int b = blockIdx.z;
    src += (size_t)b * R * C;
    const size_t dbatch = (size_t)C * (R >> 1);
    dhi += (size_t)b * dbatch;
    dlo += (size_t)b * dbatch;

    const int c0 = blockIdx.x * 32;
    const int r0 = blockIdx.y * 64;
    const int tx = threadIdx.x, ty = threadIdx.y;

    #pragma unroll
    for (int j = 0; j < 8; j++) {
        const int r = ty + 8 * j;
        s[r][tx] = src[(size_t)(r0 + r) * C + c0 + tx];
    }
    __syncthreads();

    #pragma unroll
    for (int j = 0; j < 4; j++) {
        const int cl = ty + 8 * j;
        const float x0 = s[2 * tx][cl];
        const float x1 = s[2 * tx + 1][cl];
        uint32_t hw, lw;
        split_pair_words(x0, x1, hw, lw);
        const size_t o = (size_t)(c0 + cl) * (R >> 1) + (r0 >> 1) + tx;
        dhi[o] = hw;
        dlo[o] = lw;
    }
}

// ---------------------------------------------------------------------------
// Split-fp16 tensor-core GEMM, cp.async double buffer + ldmatrix fragments.
//   C[m][n] = sum_k A[m][k] * B[n][k]  (R-layout planes)
// 128x128 CTA tile, 256 threads, 8 warps = 2(m) x 4(n), warp tile 64x32,
// m16n8k16 atoms, fp32 accumulate.
// ASINGLE/BSINGLE: operand is a single fp16 plane instead of a hi/lo split.
// MMAs per atom: 3 (both split) / 2 (one split) / 1 (both single).
// ---------------------------------------------------------------------------
template<bool BIAS, bool OSPLIT, bool ASINGLE, bool BSINGLE>
__global__ void __launch_bounds__(256, 2) bgemm(
    const uint32_t* __restrict__ Ahi32, const uint32_t* __restrict__ Alo32,
    int lda, size_t sA,
    const uint32_t* __restrict__ Bhi32, const uint32_t* __restrict__ Blo32,
    int ldb, size_t sB,
    const float* __restrict__ bias,
    float* __restrict__ C, uint32_t* __restrict__ Chi, uint32_t* __restrict__ Clo,
    int ldc, size_t sC, int Ktot)
{
    __shared__ uint32_t As[2][128 * PS];
    __shared__ uint32_t Bs[2][128 * PS];

    const int bz = blockIdx.z;
    const __half* Ahi = (const __half*)Ahi32 + sA * bz;
    const __half* Alo = (const __half*)Alo32 + sA * bz;
    const __half* Bhi = (const __half*)Bhi32 + sB * bz;
    const __half* Blo = (const __half*)Blo32 + sB * bz;

    const int tid = threadIdx.x;
    const int m0  = blockIdx.x * 128;
    const int n0  = blockIdx.y * 128;

    // cp.async loader: thread -> (row, plane); copies 2x16B per operand/stage
    const int lrow = tid >> 1;
    const int lpl  = tid & 1;
    const __half* Asrc = ((lpl && !ASINGLE) ? Alo : Ahi) + (size_t)(m0 + lrow) * lda;
    const __half* Bsrc = ((lpl && !BSINGLE) ? Blo : Bhi) + (size_t)(n0 + lrow) * ldb;
    const bool   aload = (!ASINGLE) || (lpl == 0);
    const bool   bload = (!BSINGLE) || (lpl == 0);
    const uint32_t sdst = (uint32_t)(lrow * PS + lpl * 8) * 4;   // bytes in stage

    const uint32_t aS = (uint32_t)__cvta_generic_to_shared(&As[0][0]);
    const uint32_t bS = (uint32_t)__cvta_generic_to_shared(&Bs[0][0]);
    const uint32_t stageB = 128 * PS * 4;

    // warp/lane decomposition
    const int wid = tid >> 5, lane = tid & 31;
    const int wm = (wid & 1) * 64;
    const int wn = (wid >> 1) * 32;
    const int qr = lane >> 2, qc = lane & 3;

    // ldmatrix per-lane addresses (byte offsets within a stage)
    uint32_t aoff[4], boff[4];
    {
        const int arl = (lane & 7) + (lane & 8);
        const int awd = (lane & 16) ? 4 : 0;
        #pragma unroll
        for (int mt = 0; mt < 4; mt++)
            aoff[mt] = (uint32_t)(((wm + mt * 16 + arl) * PS + awd) * 4);
        const int brl = lane & 7;
        const int bwd = BSINGLE ? (((lane >> 3) & 1) * 4)     // x2: 2 matrices
                                : (((lane >> 3) & 3) * 4);    // x4: 4 matrices
        #pragma unroll
        for (int nt = 0; nt < 4; nt++)
            boff[nt] = (uint32_t)(((wn + nt * 8 + brl) * PS + bwd) * 4);
    }

    float acc[4][4][4];
    #pragma unroll
    for (int mt = 0; mt < 4; mt++)
        #pragma unroll
        for (int nt = 0; nt < 4; nt++)
            #pragma unroll
            for (int r = 0; r < 4; r++) acc[mt][nt][r] = 0.f;

    // ---- prologue: stage 0 ----
    if (aload) {
        cpasync16(aS + sdst,      Asrc);
        cpasync16(aS + sdst + 16, Asrc + 8);
    }
    if (bload) {
        cpasync16(bS + sdst,      Bsrc);
        cpasync16(bS + sdst + 16, Bsrc + 8);
    }
    CP_COMMIT();
    CP_WAIT0();
    __syncthreads();

    const int nk = Ktot / KC;
    int buf = 0;
    for (int kb = 0; kb < nk; kb++) {
        const bool has_next = (kb + 1) < nk;
        if (has_next) {
            const int k0 = (kb + 1) * KC;
            if (aload) {
                const uint32_t ad = aS + (buf ^ 1) * stageB + sdst;
                cpasync16(ad,      Asrc + k0);
                cpasync16(ad + 16, Asrc + k0 + 8);
            }
            if (bload) {
                const uint32_t bd = bS + (buf ^ 1) * stageB + sdst;
                cpasync16(bd,      Bsrc + k0);
                cpasync16(bd + 16, Bsrc + k0 + 8);
            }
            CP_COMMIT();
        }

        const uint32_t ab = aS + buf * stageB;
        const uint32_t bb = bS + buf * stageB;

        uint32_t ah[4][4], al[4][4];
        #pragma unroll
        for (int mt = 0; mt < 4; mt++) {
            ldsm4(ah[mt], ab + aoff[mt]);              // hi plane (words 0..7)
            if (!ASINGLE)
                ldsm4(al[mt], ab + aoff[mt] + 32);     // lo plane (words 8..15)
        }
        #pragma unroll
        for (int nt = 0; nt < 4; nt++) {
            if (BSINGLE) {
                uint32_t bv[2];                        // {b0, b1} single plane
                ldsm2(bv, bb + boff[nt]);
                if (!ASINGLE) {
                    #pragma unroll
                    for (int mt = 0; mt < 4; mt++)
                        mma_f16(acc[mt][nt], al[mt], bv[0], bv[1]);   // al*b
                }
                #pragma unroll
                for (int mt = 0; mt < 4; mt++)
                    mma_f16(acc[mt][nt], ah[mt], bv[0], bv[1]);       // ah*b
            } else {
                uint32_t bv[4];                        // {b0h, b1h, b0l, b1l}
                ldsm4(bv, bb + boff[nt]);
                if (!ASINGLE) {
                    // 3-term split, term-major (reuse distance 4)
                    #pragma unroll
                    for (int mt = 0; mt < 4; mt++)
                        mma_f16(acc[mt][nt], ah[mt], bv[2], bv[3]);   // ah*bl
                    #pragma unroll
                    for (int mt = 0; mt < 4; mt++)
                        mma_f16(acc[mt][nt], al[mt], bv[0], bv[1]);   // al*bh
                    #pragma unroll
                    for (int mt = 0; mt < 4; mt++)
                        mma_f16(acc[mt][nt], ah[mt], bv[0], bv[1]);   // ah*bh
                } else {
                    #pragma unroll
                    for (int mt = 0; mt < 4; mt++)
                        mma_f16(acc[mt][nt], ah[mt], bv[2], bv[3]);   // a*bl
                    #pragma unroll
                    for (int mt = 0; mt < 4; mt++)
                        mma_f16(acc[mt][nt], ah[mt], bv[0], bv[1]);   // a*bh
                }
            }
        }

        if (has_next) {
            CP_WAIT0();
            __syncthreads();
            buf ^= 1;
        }
    }

    // ---- epilogue ----
    #pragma unroll
    for (int mt = 0; mt < 4; mt++) {
        #pragma unroll
        for (int nt = 0; nt < 4; nt++) {
            const int row = m0 + wm + mt * 16 + qr;
            const int col = n0 + wn + nt * 8 + 2 * qc;
            float v0 = acc[mt][nt][0], v1 = acc[mt][nt][1];
            float v2 = acc[mt][nt][2], v3 = acc[mt][nt][3];
            if (BIAS) {
                const float b0 = bias[col], b1 = bias[col + 1];
                v0 += b0; v1 += b1; v2 += b0; v3 += b1;
            }
            if (OSPLIT) {
                uint32_t* chb = Chi + (size_t)bz * (sC >> 1);
                uint32_t* clb = Clo + (size_t)bz * (sC >> 1);
                uint32_t hw, lw;
                split_pair_words(v0, v1, hw, lw);
                size_t o = (size_t)row * (ldc >> 1) + (col >> 1);
                chb[o] = hw; clb[o] = lw;
                split_pair_words(v2, v3, hw, lw);
                o = (size_t)(row + 8) * (ldc >> 1) + (col >> 1);
                chb[o] = hw; clb[o] = lw;
            } else {
                float* cb = C + sC * bz;
                *(float2*)&cb[(size_t)row * ldc + col]       = make_float2(v0, v1);
                *(float2*)&cb[(size_t)(row + 8) * ldc + col] = make_float2(v2, v3);
            }
        }
    }
}

// ---------------------------------------------------------------------------
// Fused row softmax + fp16 quantize: S[b][i][p] fp32 -> single prob plane.
// One CTA per row (2304 elements cached in smem), 256 threads.
// ---------------------------------------------------------------------------
__global__ void __launch_bounds__(256) softmax_split(
    const float* __restrict__ S,
    uint32_t* __restrict__ ph_out)
{
    __shared__ float row[NP];
    __shared__ float red[9];
    const int b = blockIdx.y, i = blockIdx.x, t = threadIdx.x;
    const int wid = t >> 5, lane = t & 31;
    const float* src = S + ((size_t)b * NP + i) * NP;

    float lm = -3.402823466e38f;
    #pragma unroll
    for (int j = 0; j < 9; j++) {
        const int idx = j * 256 + t;
        const float x = src[idx];
        row[idx] = x;
        lm = fmaxf(lm, x);
    }
    #pragma unroll
    for (int o = 16; o; o >>= 1) lm = fmaxf(lm, __shfl_xor_sync(0xffffffffu, lm, o));
    if (lane == 0) red[wid] = lm;
    __syncthreads();
    if (t == 0) {
        float M = red[0];
        #pragma unroll
        for (int k = 1; k < 8; k++) M = fmaxf(M, red[k]);
        red[8] = M;
    }
    __syncthreads();
    const float M = red[8];

    float ls = 0.f;
    #pragma unroll
    for (int j = 0; j < 9; j++) {
        const int idx = j * 256 + t;
        const float e = __expf(row[idx] - M);
        row[idx] = e;
        ls += e;
    }
    #pragma unroll
    for (int o = 16; o; o >>= 1) ls += __shfl_xor_sync(0xffffffffu, ls, o);
    if (lane == 0) red[wid] = ls;
    __syncthreads();
    if (t == 0) {
        float s2 = 0.f;
        #pragma unroll
        for (int k = 0; k < 8; k++) s2 += red[k];
        red[8] = 1.0f / s2;
    }
    __syncthreads();
    const float inv = red[8];

    uint32_t* oh = ph_out + ((size_t)b * NP + i) * (NP / 2);
    #pragma unroll
    for (int j = 0; j < 5; j++) {
        const int q = j * 256 + t;
        if (q < NP / 2) {
            const float2 xv = *(const float2*)&row[2 * q];
            const __half2 h2 = __floats2half2_rn(xv.x * inv, xv.y * inv);
            oh[q] = *(const uint32_t*)&h2;
        }
    }
}

// ---------------------------------------------------------------------------
extern "C" void kernel_launch(void* const* d_in, const int* in_sizes, int n_in,
                              void* d_out, int out_size)
{
    const float* qf = (const float*)d_in[0];   // [B, CQ, 48, 48]
    const float* rf = (const float*)d_in[1];   // [B, CR, 48, 48]
    const float* Wq = (const float*)d_in[2];   // [HID, CQ]
    const float* bq = (const float*)d_in[3];   // [HID]
    const float* Wk = (const float*)d_in[4];   // [HID, CR]
    const float* bk = (const float*)d_in[5];   // [HID]
    float* out = (float*)d_out;                // [B, CR, 48, 48]

    uint32_t *qfTh, *qfTl, *rfTh, *rfTl, *rfS;
    uint32_t *Wqh, *Wql, *Wkh, *Wkl, *Qh, *Ql, *Kh, *Kl, *ath;
    float *Ap;
    cudaGetSymbolAddress((void**)&qfTh, g_qfT_hi);
    cudaGetSymbolAddress((void**)&qfTl, g_qfT_lo);
    cudaGetSymbolAddress((void**)&rfTh, g_rfT_hi);
    cudaGetSymbolAddress((void**)&rfTl, g_rfT_lo);
    cudaGetSymbolAddress((void**)&rfS, g_rfS);
    cudaGetSymbolAddress((void**)&Wqh, g_Wq_hi);
    cudaGetSymbolAddress((void**)&Wql, g_Wq_lo);
    cudaGetSymbolAddress((void**)&Wkh, g_Wk_hi);
    cudaGetSymbolAddress((void**)&Wkl, g_Wk_lo);
    cudaGetSymbolAddress((void**)&Qh, g_Q_hi);
    cudaGetSymbolAddress((void**)&Ql, g_Q_lo);
    cudaGetSymbolAddress((void**)&Kh, g_K_hi);
    cudaGetSymbolAddress((void**)&Kl, g_K_lo);
    cudaGetSymbolAddress((void**)&ath, g_at);
    cudaGetSymbolAddress((void**)&Ap, g_attn);

    // ---- prepass: splits + transposes ----
    {
        size_t np;
        np = (size_t)HID * CQ / 2;
        split_pairs<<<(unsigned)((np + 255) / 256), 256>>>(Wq, Wqh, Wql, np);
        np = (size_t)HID * CR / 2;
        split_pairs<<<(unsigned)((np + 255) / 256), 256>>>(Wk, Wkh, Wkl, np);
        np = (size_t)BB * CR * NP / 2;
        cvt_pairs<<<(unsigned)((np + 255) / 256), 256>>>(rf, rfS, np);   // V single plane
    }
    transpose_split<<<dim3(NP / 32, CQ / 64, BB), dim3(32, 8)>>>(qf, qfTh, qfTl, CQ, NP);
    transpose_split<<<dim3(NP / 32, CR / 64, BB), dim3(32, 8)>>>(rf, rfTh, rfTl, CR, NP);

    // ---- GEMM1: Q[i][o] = qfT[i][c] * Wq[o][c] + bq -> hi/lo planes ----
    bgemm<true, true, false, false><<<dim3(NP / 128, HID / 128, BB), 256>>>(
        qfTh, qfTl, CQ, (size_t)NP * CQ,
        Wqh, Wql, CQ, 0,
        bq,
        nullptr, Qh, Ql, HID, (size_t)NP * HID,
        CQ);

    // ---- GEMM2: K[p][o] = rfT[p][c] * Wk[o][c] + bk -> hi/lo planes ----
    bgemm<true, true, false, false><<<dim3(NP / 128, HID / 128, BB), 256>>>(
        rfTh, rfTl, CR, (size_t)NP * CR,
        Wkh, Wkl, CR, 0,
        bk,
        nullptr, Kh, Kl, HID, (size_t)NP * HID,
        CR);

    // ---- GEMM3: S[i][p] = Q[i][k] * K[p][k]  (fp32 out, 3-term) ----
    bgemm<false, false, false, false><<<dim3(NP / 128, NP / 128, BB), 256>>>(
        Qh, Ql, HID, (size_t)NP * HID,
        Kh, Kl, HID, (size_t)NP * HID,
        nullptr,
        Ap, nullptr, nullptr, NP, (size_t)NP * NP,
        HID);

    // ---- fused softmax over p -> single fp16 prob plane [i][p] ----
    softmax_split<<<dim3(NP, BB), 256>>>(Ap, ath);

    // ---- GEMM4: out[c][i] = V[c][p] * attn[i][p]; both single, 1 MMA/atom ----
    bgemm<false, false, true, true><<<dim3(CR / 128, NP / 128, BB), 256>>>(
        rfS, rfS, NP, (size_t)CR * NP,
        ath, ath, NP, (size_t)NP * NP,
        nullptr,
        out, nullptr, nullptr, NP, (size_t)CR * NP,
        NP);
}

// round 13
// speedup vs baseline: 1.6207x; 1.0079x over previous
#include <cuda_runtime.h>
#include <cuda_fp16.h>
#include <math.h>
#include <float.h>
#include <stdint.h>

// Problem constants
#define BB   8
#define CQ   1024
#define CR   512
#define HID  256
#define NP   2304          // H*W = 48*48
#define NBLK 18            // NP / 128 p-blocks

#define KC   16            // k per smem stage

// ---------------------------------------------------------------------------
// Device-global scratch. "Planes" are fp16 hi/lo pairs packed in u32.
// ---------------------------------------------------------------------------
__device__ uint32_t g_qfT_hi[(size_t)BB * NP * CQ / 2];   // [b][i][c]
__device__ uint32_t g_qfT_lo[(size_t)BB * NP * CQ / 2];
__device__ uint32_t g_rfT_hi[(size_t)BB * NP * CR / 2];   // [b][p][c]
__device__ uint32_t g_rfT_lo[(size_t)BB * NP * CR / 2];
__device__ uint32_t g_rfS[(size_t)BB * CR * NP / 2];      // [b][c][p] V, single fp16
__device__ uint32_t g_Wq_hi[(size_t)HID * CQ / 2];
__device__ uint32_t g_Wq_lo[(size_t)HID * CQ / 2];
__device__ uint32_t g_Wk_hi[(size_t)HID * CR / 2];
__device__ uint32_t g_Wk_lo[(size_t)HID * CR / 2];
__device__ uint32_t g_Q_hi[(size_t)BB * NP * HID / 2];    // [b][i][o]
__device__ uint32_t g_Q_lo[(size_t)BB * NP * HID / 2];
__device__ uint32_t g_K_hi[(size_t)BB * NP * HID / 2];    // [b][p][o]
__device__ uint32_t g_K_lo[(size_t)BB * NP * HID / 2];
__device__ uint32_t g_at[(size_t)BB * NP * NP / 2];       // [b][i][p] exp(x-lmax), fp16
__device__ float    g_lmax[(size_t)BB * NP * NBLK];       // per (row, p-block) max
__device__ float    g_lsum[(size_t)BB * NP * NBLK];       // per (row, p-block) sum
__device__ float    g_scale[(size_t)BB * NP * NBLK];      // exp(lmax-M)/S

// ---------------------------------------------------------------------------
// helpers
// ---------------------------------------------------------------------------
__device__ __forceinline__ void split_f16(float x, unsigned short &h, unsigned short &l) {
    __half hb = __float2half_rn(x);
    h = __half_as_ushort(hb);
    float r = x - __half2float(hb);
    l = __half_as_ushort(__float2half_rn(r));
}
__device__ __forceinline__ void split_pair_words(float x0, float x1,
                                                 uint32_t &hw, uint32_t &lw) {
    unsigned short h0, l0, h1, l1;
    split_f16(x0, h0, l0);
    split_f16(x1, h1, l1);
    hw = (uint32_t)h0 | ((uint32_t)h1 << 16);
    lw = (uint32_t)l0 | ((uint32_t)l1 << 16);
}
__device__ __forceinline__ uint32_t pack_h2(float x0, float x1) {
    const __half2 h2 = __floats2half2_rn(x0, x1);
    return *(const uint32_t*)&h2;
}

// fp16 inputs, fp32 accumulate
__device__ __forceinline__ void mma_f16(float c[4], const uint32_t a[4],
                                        const uint32_t b0, const uint32_t b1) {
    asm volatile(
        "mma.sync.aligned.m16n8k16.row.col.f32.f16.f16.f32 "
        "{%0,%1,%2,%3}, {%4,%5,%6,%7}, {%8,%9}, {%0,%1,%2,%3};\n"
        : "+f"(c[0]), "+f"(c[1]), "+f"(c[2]), "+f"(c[3])
        : "r"(a[0]), "r"(a[1]), "r"(a[2]), "r"(a[3]),
          "r"(b0), "r"(b1));
}

__device__ __forceinline__ void ldsm4(uint32_t r[4], uint32_t addr) {
    asm volatile("ldmatrix.sync.aligned.m8n8.x4.shared.b16 {%0,%1,%2,%3}, [%4];"
                 : "=r"(r[0]), "=r"(r[1]), "=r"(r[2]), "=r"(r[3]) : "r"(addr));
}
__device__ __forceinline__ void ldsm2(uint32_t r[2], uint32_t addr) {
    asm volatile("ldmatrix.sync.aligned.m8n8.x2.shared.b16 {%0,%1}, [%2];"
                 : "=r"(r[0]), "=r"(r[1]) : "r"(addr));
}
__device__ __forceinline__ void cpasync16(uint32_t saddr, const void* g) {
    asm volatile("cp.async.cg.shared.global [%0], [%1], 16;" :: "r"(saddr), "l"(g));
}
#define CP_COMMIT() asm volatile("cp.async.commit_group;" ::: "memory")
#define CP_WAIT0()  asm volatile("cp.async.wait_group 0;" ::: "memory")

// ---------------------------------------------------------------------------
// Elementwise split: fp32 -> hi/lo fp16 planes (pairs packed in u32).
// ---------------------------------------------------------------------------
__global__ void __launch_bounds__(256) split_pairs(
    const float* __restrict__ src,
    uint32_t* __restrict__ dhi, uint32_t* __restrict__ dlo, size_t npairs)
{
    size_t i = (size_t)blockIdx.x * 256 + threadIdx.x;
    if (i >= npairs) return;
    uint32_t hw, lw;
    split_pair_words(src[2 * i], src[2 * i + 1], hw, lw);
    dhi[i] = hw;
    dlo[i] = lw;
}

// ---------------------------------------------------------------------------
// Elementwise convert: fp32 -> single fp16 plane (pairs packed in u32).
// ---------------------------------------------------------------------------
__global__ void __launch_bounds__(256) cvt_pairs(
    const float* __restrict__ src,
    uint32_t* __restrict__ dst, size_t npairs)
{
    size_t i = (size_t)blockIdx.x * 256 + threadIdx.x;
    if (i >= npairs) return;
    dst[i] = pack_h2(src[2 * i], src[2 * i + 1]);
}

// ---------------------------------------------------------------------------
// Tiled transpose + split: src fp32 [R][C] -> dst hi/lo fp16 [C][R].
// ---------------------------------------------------------------------------
__global__ void __launch_bounds__(256) transpose_split(
    const float* __restrict__ src,
    uint32_t* __restrict__ dhi, uint32_t* __restrict__ dlo,
    int R, int C)
{
    __shared__ float s[64][33];
    const int b = blockIdx.z;
    src += (size_t)b * R * C;
    const size_t dbatch = (size_t)C * (R >> 1);
    dhi += (size_t)b * dbatch;
    dlo += (size_t)b * dbatch;

    const int c0 = blockIdx.x * 32;
    const int r0 = blockIdx.y * 64;
    const int tx = threadIdx.x, ty = threadIdx.y;

    #pragma unroll
    for (int j = 0; j < 8; j++) {
        const int r = ty + 8 * j;
        s[r][tx] = src[(size_t)(r0 + r) * C + c0 + tx];
    }
    __syncthreads();

    #pragma unroll
    for (int j = 0; j < 4; j++) {
        const int cl = ty + 8 * j;
        uint32_t hw, lw;
        split_pair_words(s[2 * tx][cl], s[2 * tx + 1][cl], hw, lw);
        const size_t o = (size_t)(c0 + cl) * (R >> 1) + (r0 >> 1) + tx;
        dhi[o] = hw;
        dlo[o] = lw;
    }
}

// ---------------------------------------------------------------------------
// Split-fp16 tensor-core GEMM, cp.async double buffer + ldmatrix fragments.
//   C[m][n] = sum_k A[m][k] * B[n][k]  (R-layout planes)
// 128x128 CTA tile, 256 threads, 8 warps = 2(m) x 4(n), warp tile 64x32.
// ASINGLE/BSINGLE: operand is a single fp16 plane (1 ldsm, smaller smem).
// OMODE: 0 = fp32 store, 1 = hi/lo split store,
//        2 = flash epilogue: per-(row, CTA-p-block) max/sum stats + fp16 exp.
// BSCALE: B fragments scaled inline by per-(n,kblock) softmax scales (smem).
// ---------------------------------------------------------------------------
template<bool BIAS, int OMODE, bool ASINGLE, bool BSINGLE, bool BSCALE>
__global__ void __launch_bounds__(256, 2) bgemm(
    const uint32_t* __restrict__ Ahi32, const uint32_t* __restrict__ Alo32,
    int lda, size_t sA,
    const uint32_t* __restrict__ Bhi32, const uint32_t* __restrict__ Blo32,
    int ldb, size_t sB,
    const float* __restrict__ bias,
    float* __restrict__ C, uint32_t* __restrict__ Chi, uint32_t* __restrict__ Clo,
    int ldc, size_t sC, int Ktot,
    float* __restrict__ lmax_out, float* __restrict__ lsum_out,
    const float* __restrict__ bscale)
{
    constexpr int APS = ASINGLE ? 12 : 20;   // smem words per A row (8 data + pad)
    constexpr int BPS = BSINGLE ? 12 : 20;
    __shared__ uint32_t As[2][128 * APS];
    __shared__ uint32_t Bs[2][128 * BPS];
    __shared__ float red[OMODE == 2 ? 4 : 1][OMODE == 2 ? 128 : 1];
    __shared__ float sscale[BSCALE ? 128 * NBLK : 1];

    const int bz = blockIdx.z;
    const __half* Ahi = (const __half*)Ahi32 + sA * bz;
    const __half* Alo = (const __half*)Alo32 + sA * bz;
    const __half* Bhi = (const __half*)Bhi32 + sB * bz;
    const __half* Blo = (const __half*)Blo32 + sB * bz;

    const int tid = threadIdx.x;
    const int m0  = blockIdx.x * 128;
    const int n0  = blockIdx.y * 128;

    // cp.async loader: thread -> (row, plane); 2x16B per loaded plane/stage
    const int lrow = tid >> 1;
    const int lpl  = tid & 1;
    const __half* Asrc = ((lpl && !ASINGLE) ? Alo : Ahi) + (size_t)(m0 + lrow) * lda;
    const __half* Bsrc = ((lpl && !BSINGLE) ? Blo : Bhi) + (size_t)(n0 + lrow) * ldb;
    const bool   aload = (!ASINGLE) || (lpl == 0);
    const bool   bload = (!BSINGLE) || (lpl == 0);
    const uint32_t sdstA = (uint32_t)(lrow * APS + lpl * 8) * 4;
    const uint32_t sdstB = (uint32_t)(lrow * BPS + lpl * 8) * 4;

    const uint32_t aS = (uint32_t)__cvta_generic_to_shared(&As[0][0]);
    const uint32_t bS = (uint32_t)__cvta_generic_to_shared(&Bs[0][0]);
    const uint32_t stageA = 128 * APS * 4;
    const uint32_t stageB = 128 * BPS * 4;

    // warp/lane decomposition
    const int wid = tid >> 5, lane = tid & 31;
    const int wm = (wid & 1) * 64;
    const int wn = (wid >> 1) * 32;
    const int qr = lane >> 2, qc = lane & 3;

    // ldmatrix per-lane addresses (byte offsets within a stage)
    uint32_t aoff[4], boff[4];
    {
        const int arl = (lane & 7) + (lane & 8);
        const int awd = (lane & 16) ? 4 : 0;
        #pragma unroll
        for (int mt = 0; mt < 4; mt++)
            aoff[mt] = (uint32_t)(((wm + mt * 16 + arl) * APS + awd) * 4);
        const int brl = lane & 7;
        const int bwd = BSINGLE ? (((lane >> 3) & 1) * 4)
                                : (((lane >> 3) & 3) * 4);
        #pragma unroll
        for (int nt = 0; nt < 4; nt++)
            boff[nt] = (uint32_t)(((wn + nt * 8 + brl) * BPS + bwd) * 4);
    }

    // preload softmax scales for this CTA's n-range
    if (BSCALE) {
        const size_t sb0 = ((size_t)bz * (size_t)(gridDim.y * 128) + n0) * NBLK;
        for (int idx = tid; idx < 128 * NBLK; idx += 256)
            sscale[idx] = bscale[sb0 + idx];
    }

    float acc[4][4][4];
    #pragma unroll
    for (int mt = 0; mt < 4; mt++)
        #pragma unroll
        for (int nt = 0; nt < 4; nt++)
            #pragma unroll
            for (int r = 0; r < 4; r++) acc[mt][nt][r] = 0.f;

    // ---- prologue: stage 0 ----
    if (aload) {
        cpasync16(aS + sdstA,      Asrc);
        cpasync16(aS + sdstA + 16, Asrc + 8);
    }
    if (bload) {
        cpasync16(bS + sdstB,      Bsrc);
        cpasync16(bS + sdstB + 16, Bsrc + 8);
    }
    CP_COMMIT();
    CP_WAIT0();
    __syncthreads();

    const int nk = Ktot / KC;
    int buf = 0;
    for (int kb = 0; kb < nk; kb++) {
        const bool has_next = (kb + 1) < nk;
        if (has_next) {
            const int k0 = (kb + 1) * KC;
            if (aload) {
                const uint32_t ad = aS + (buf ^ 1) * stageA + sdstA;
                cpasync16(ad,      Asrc + k0);
                cpasync16(ad + 16, Asrc + k0 + 8);
            }
            if (bload) {
                const uint32_t bd = bS + (buf ^ 1) * stageB + sdstB;
                cpasync16(bd,      Bsrc + k0);
                cpasync16(bd + 16, Bsrc + k0 + 8);
            }
            CP_COMMIT();
        }

        const uint32_t ab = aS + buf * stageA;
        const uint32_t bb = bS + buf * stageB;

        uint32_t ah[4][4], al[4][4];
        #pragma unroll
        for (int mt = 0; mt < 4; mt++) {
            ldsm4(ah[mt], ab + aoff[mt]);
            if (!ASINGLE)
                ldsm4(al[mt], ab + aoff[mt] + 32);
        }
        #pragma unroll
        for (int nt = 0; nt < 4; nt++) {
            if (BSINGLE) {
                uint32_t bv[2];
                ldsm2(bv, bb + boff[nt]);
                if (BSCALE) {
                    // both fragment elements share n = wn+nt*8+(lane>>2);
                    // 16-k chunk lies in one 128-p block -> one scale
                    const float s = sscale[(wn + nt * 8 + (lane >> 2)) * NBLK + (kb >> 3)];
                    const __half2 hs = __float2half2_rn(s);
                    *(__half2*)&bv[0] = __hmul2(*(const __half2*)&bv[0], hs);
                    *(__half2*)&bv[1] = __hmul2(*(const __half2*)&bv[1], hs);
                }
                if (!ASINGLE) {
                    #pragma unroll
                    for (int mt = 0; mt < 4; mt++)
                        mma_f16(acc[mt][nt], al[mt], bv[0], bv[1]);
                }
                #pragma unroll
                for (int mt = 0; mt < 4; mt++)
                    mma_f16(acc[mt][nt], ah[mt], bv[0], bv[1]);
            } else {
                uint32_t bv[4];
                ldsm4(bv, bb + boff[nt]);
                if (!ASINGLE) {
                    #pragma unroll
                    for (int mt = 0; mt < 4; mt++)
                        mma_f16(acc[mt][nt], ah[mt], bv[2], bv[3]);   // ah*bl
                    #pragma unroll
                    for (int mt = 0; mt < 4; mt++)
                        mma_f16(acc[mt][nt], al[mt], bv[0], bv[1]);   // al*bh
                    #pragma unroll
                    for (int mt = 0; mt < 4; mt++)
                        mma_f16(acc[mt][nt], ah[mt], bv[0], bv[1]);   // ah*bh
                } else {
                    #pragma unroll
                    for (int mt = 0; mt < 4; mt++)
                        mma_f16(acc[mt][nt], ah[mt], bv[2], bv[3]);
                    #pragma unroll
                    for (int mt = 0; mt < 4; mt++)
                        mma_f16(acc[mt][nt], ah[mt], bv[0], bv[1]);
                }
            }
        }

        if (has_next) {
            CP_WAIT0();
            __syncthreads();
            buf ^= 1;
        }
    }

    // ---- epilogue ----
    if (OMODE == 2) {
        // flash epilogue: per-row block max / exp / sum, fp16 exp store
        const int wni = wid >> 1;
        float rmax[8];
        #pragma unroll
        for (int j = 0; j < 8; j++) rmax[j] = -FLT_MAX;
        #pragma unroll
        for (int mt = 0; mt < 4; mt++)
            #pragma unroll
            for (int nt = 0; nt < 4; nt++) {
                rmax[mt * 2 + 0] = fmaxf(rmax[mt * 2 + 0],
                                         fmaxf(acc[mt][nt][0], acc[mt][nt][1]));
                rmax[mt * 2 + 1] = fmaxf(rmax[mt * 2 + 1],
                                         fmaxf(acc[mt][nt][2], acc[mt][nt][3]));
            }
        #pragma unroll
        for (int j = 0; j < 8; j++) {
            rmax[j] = fmaxf(rmax[j], __shfl_xor_sync(0xffffffffu, rmax[j], 1));
            rmax[j] = fmaxf(rmax[j], __shfl_xor_sync(0xffffffffu, rmax[j], 2));
        }
        if (qc == 0)
            #pragma unroll
            for (int mt = 0; mt < 4; mt++)
                #pragma unroll
                for (int h = 0; h < 2; h++)
                    red[wni][wm + mt * 16 + qr + 8 * h] = rmax[mt * 2 + h];
        __syncthreads();
        float fm[8];
        #pragma unroll
        for (int mt = 0; mt < 4; mt++)
            #pragma unroll
            for (int h = 0; h < 2; h++) {
                const int rl = wm + mt * 16 + qr + 8 * h;
                fm[mt * 2 + h] = fmaxf(fmaxf(red[0][rl], red[1][rl]),
                                       fmaxf(red[2][rl], red[3][rl]));
            }
        __syncthreads();

        float rs[8];
        #pragma unroll
        for (int j = 0; j < 8; j++) rs[j] = 0.f;
        uint32_t* chb = Chi + (size_t)bz * (sC >> 1);
        #pragma unroll
        for (int mt = 0; mt < 4; mt++)
            #pragma unroll
            for (int nt = 0; nt < 4; nt++) {
                const int col = n0 + wn + nt * 8 + 2 * qc;
                #pragma unroll
                for (int h = 0; h < 2; h++) {
                    const float e0 = __expf(acc[mt][nt][2 * h + 0] - fm[mt * 2 + h]);
                    const float e1 = __expf(acc[mt][nt][2 * h + 1] - fm[mt * 2 + h]);
                    const int row = m0 + wm + mt * 16 + qr + 8 * h;
                    chb[(size_t)row * (ldc >> 1) + (col >> 1)] = pack_h2(e0, e1);
                    rs[mt * 2 + h] += e0 + e1;
                }
            }
        #pragma unroll
        for (int j = 0; j < 8; j++) {
            rs[j] += __shfl_xor_sync(0xffffffffu, rs[j], 1);
            rs[j] += __shfl_xor_sync(0xffffffffu, rs[j], 2);
        }
        if (qc == 0)
            #pragma unroll
            for (int mt = 0; mt < 4; mt++)
                #pragma unroll
                for (int h = 0; h < 2; h++)
                    red[wni][wm + mt * 16 + qr + 8 * h] = rs[mt * 2 + h];
        __syncthreads();
        if (wni == 0 && qc == 0) {
            const size_t mtot = (size_t)gridDim.x * 128;
            #pragma unroll
            for (int mt = 0; mt < 4; mt++)
                #pragma unroll
                for (int h = 0; h < 2; h++) {
                    const int rl = wm + mt * 16 + qr + 8 * h;
                    const float sm = red[0][rl] + red[1][rl] + red[2][rl] + red[3][rl];
                    const size_t o = ((size_t)bz * mtot + m0 + rl) * NBLK + blockIdx.y;
                    lmax_out[o] = fm[mt * 2 + h];
                    lsum_out[o] = sm;
                }
        }
    } else {
        #pragma unroll
        for (int mt = 0; mt < 4; mt++) {
            #pragma unroll
            for (int nt = 0; nt < 4; nt++) {
                const int row = m0 + wm + mt * 16 + qr;
                const int col = n0 + wn + nt * 8 + 2 * qc;
                float v0 = acc[mt][nt][0], v1 = acc[mt][nt][1];
                float v2 = acc[mt][nt][2], v3 = acc[mt][nt][3];
                if (BIAS) {
                    const float b0 = bias[col], b1 = bias[col + 1];
                    v0 += b0; v1 += b1; v2 += b0; v3 += b1;
                }
                if (OMODE == 1) {
                    uint32_t* chb = Chi + (size_t)bz * (sC >> 1);
                    uint32_t* clb = Clo + (size_t)bz * (sC >> 1);
                    uint32_t hw, lw;
                    split_pair_words(v0, v1, hw, lw);
                    size_t o = (size_t)row * (ldc >> 1) + (col >> 1);
                    chb[o] = hw; clb[o] = lw;
                    split_pair_words(v2, v3, hw, lw);
                    o = (size_t)(row + 8) * (ldc >> 1) + (col >> 1);
                    chb[o] = hw; clb[o] = lw;
                } else {
                    float* cb = C + sC * bz;
                    *(float2*)&cb[(size_t)row * ldc + col]       = make_float2(v0, v1);
                    *(float2*)&cb[(size_t)(row + 8) * ldc + col] = make_float2(v2, v3);
                }
            }
        }
    }
}

// ---------------------------------------------------------------------------
// Combine per-block softmax stats -> per-(row, block) scale = exp(lmax-M)/S.
// One thread per row; 18 blocks per row.
// ---------------------------------------------------------------------------
__global__ void __launch_bounds__(256) combine_stats(
    const float* __restrict__ lmax, const float* __restrict__ lsum,
    float* __restrict__ scale)
{
    const int r = blockIdx.x * 256 + threadIdx.x;
    if (r >= BB * NP) return;
    const float* lm = lmax + (size_t)r * NBLK;
    const float* ls = lsum + (size_t)r * NBLK;
    float M = -FLT_MAX;
    #pragma unroll
    for (int j = 0; j < NBLK; j++) M = fmaxf(M, lm[j]);
    float e[NBLK], S = 0.f;
    #pragma unroll
    for (int j = 0; j < NBLK; j++) {
        e[j] = __expf(lm[j] - M);
        S += ls[j] * e[j];
    }
    const float inv = 1.0f / S;
    float* sc = scale + (size_t)r * NBLK;
    #pragma unroll
    for (int j = 0; j < NBLK; j++) sc[j] = e[j] * inv;
}

// ---------------------------------------------------------------------------
extern "C" void kernel_launch(void* const* d_in, const int* in_sizes, int n_in,
                              void* d_out, int out_size)
{
    const float* qf = (const float*)d_in[0];   // [B, CQ, 48, 48]
    const float* rf = (const float*)d_in[1];   // [B, CR, 48, 48]
    const float* Wq = (const float*)d_in[2];   // [HID, CQ]
    const float* bq = (const float*)d_in[3];   // [HID]
    const float* Wk = (const float*)d_in[4];   // [HID, CR]
    const float* bk = (const float*)d_in[5];   // [HID]
    float* out = (float*)d_out;                // [B, CR, 48, 48]

    uint32_t *qfTh, *qfTl, *rfTh, *rfTl, *rfS;
    uint32_t *Wqh, *Wql, *Wkh, *Wkl, *Qh, *Ql, *Kh, *Kl, *ath;
    float *lmx, *lsm, *scl;
    cudaGetSymbolAddress((void**)&qfTh, g_qfT_hi);
    cudaGetSymbolAddress((void**)&qfTl, g_qfT_lo);
    cudaGetSymbolAddress((void**)&rfTh, g_rfT_hi);
    cudaGetSymbolAddress((void**)&rfTl, g_rfT_lo);
    cudaGetSymbolAddress((void**)&rfS, g_rfS);
    cudaGetSymbolAddress((void**)&Wqh, g_Wq_hi);
    cudaGetSymbolAddress((void**)&Wql, g_Wq_lo);
    cudaGetSymbolAddress((void**)&Wkh, g_Wk_hi);
    cudaGetSymbolAddress((void**)&Wkl, g_Wk_lo);
    cudaGetSymbolAddress((void**)&Qh, g_Q_hi);
    cudaGetSymbolAddress((void**)&Ql, g_Q_lo);
    cudaGetSymbolAddress((void**)&Kh, g_K_hi);
    cudaGetSymbolAddress((void**)&Kl, g_K_lo);
    cudaGetSymbolAddress((void**)&ath, g_at);
    cudaGetSymbolAddress((void**)&lmx, g_lmax);
    cudaGetSymbolAddress((void**)&lsm, g_lsum);
    cudaGetSymbolAddress((void**)&scl, g_scale);

    // ---- prepass: splits + transposes ----
    {
        size_t np;
        np = (size_t)HID * CQ / 2;
        split_pairs<<<(unsigned)((np + 255) / 256), 256>>>(Wq, Wqh, Wql, np);
        np = (size_t)HID * CR / 2;
        split_pairs<<<(unsigned)((np + 255) / 256), 256>>>(Wk, Wkh, Wkl, np);
        np = (size_t)BB * CR * NP / 2;
        cvt_pairs<<<(unsigned)((np + 255) / 256), 256>>>(rf, rfS, np);
    }
    transpose_split<<<dim3(NP / 32, CQ / 64, BB), dim3(32, 8)>>>(qf, qfTh, qfTl, CQ, NP);
    transpose_split<<<dim3(NP / 32, CR / 64, BB), dim3(32, 8)>>>(rf, rfTh, rfTl, CR, NP);

    // ---- GEMM1: Q[i][o] = qfT[i][c] * Wq[o][c] + bq -> hi/lo planes ----
    bgemm<true, 1, false, false, false><<<dim3(NP / 128, HID / 128, BB), 256>>>(
        qfTh, qfTl, CQ, (size_t)NP * CQ,
        Wqh, Wql, CQ, 0,
        bq,
        nullptr, Qh, Ql, HID, (size_t)NP * HID,
        CQ, nullptr, nullptr, nullptr);

    // ---- GEMM2: K[p][o] = rfT[p][c] * Wk[o][c] + bk -> hi/lo planes ----
    bgemm<true, 1, false, false, false><<<dim3(NP / 128, HID / 128, BB), 256>>>(
        rfTh, rfTl, CR, (size_t)NP * CR,
        Wkh, Wkl, CR, 0,
        bk,
        nullptr, Kh, Kl, HID, (size_t)NP * HID,
        CR, nullptr, nullptr, nullptr);

    // ---- GEMM3: S[i][p] = Q[i][k] * K[p][k]; flash epilogue ->
    //      fp16 exp(x - blockmax) [i][p] + per-block (max, sum) stats ----
    bgemm<false, 2, false, false, false><<<dim3(NP / 128, NP / 128, BB), 256>>>(
        Qh, Ql, HID, (size_t)NP * HID,
        Kh, Kl, HID, (size_t)NP * HID,
        nullptr,
        nullptr, ath, nullptr, NP, (size_t)NP * NP,
        HID, lmx, lsm, nullptr);

    // ---- combine per-block stats -> scales ----
    combine_stats<<<(BB * NP + 255) / 256, 256>>>(lmx, lsm, scl);

    // ---- GEMM4: out[c][i] = V[c][p] * exp[i][p] * scale[i][blk(p)];
    //      single planes, inline B scaling, 1 MMA/atom ----
    bgemm<false, 0, true, true, true><<<dim3(CR / 128, NP / 128, BB), 256>>>(
        rfS, rfS, NP, (size_t)CR * NP,
        ath, ath, NP, (size_t)NP * NP,
        nullptr,
        out, nullptr, nullptr, NP, (size_t)CR * NP,
        NP, nullptr, nullptr, scl);
}

// round 14
// speedup vs baseline: 1.8000x; 1.1106x over previous
#include <cuda_runtime.h>
#include <cuda_fp16.h>
#include <math.h>
#include <float.h>
#include <stdint.h>

// Problem constants
#define BB   8
#define CQ   1024
#define CR   512
#define HID  256
#define NP   2304          // H*W = 48*48
#define NBLK 18            // NP / 128 p-blocks

#define KC   16            // k per smem stage
#define TPS  68            // T-layout smem words per k-row (64 data + 4 pad)

// ---------------------------------------------------------------------------
// Device-global scratch. "Planes" are fp16 hi/lo pairs packed in u32.
// ---------------------------------------------------------------------------
__device__ uint32_t g_rfS[(size_t)BB * CR * NP / 2];      // [b][c][p] V, single fp16
__device__ uint32_t g_Wq_hi[(size_t)HID * CQ / 2];
__device__ uint32_t g_Wq_lo[(size_t)HID * CQ / 2];
__device__ uint32_t g_Wk_hi[(size_t)HID * CR / 2];
__device__ uint32_t g_Wk_lo[(size_t)HID * CR / 2];
__device__ uint32_t g_Q_hi[(size_t)BB * NP * HID / 2];    // [b][i][o]
__device__ uint32_t g_Q_lo[(size_t)BB * NP * HID / 2];
__device__ uint32_t g_K_hi[(size_t)BB * NP * HID / 2];    // [b][p][o]
__device__ uint32_t g_K_lo[(size_t)BB * NP * HID / 2];
__device__ uint32_t g_at[(size_t)BB * NP * NP / 2];       // [b][i][p] exp(x-lmax), fp16
__device__ float    g_lmax[(size_t)BB * NP * NBLK];       // per (row, p-block) max
__device__ float    g_lsum[(size_t)BB * NP * NBLK];       // per (row, p-block) sum
__device__ float    g_scale[(size_t)BB * NP * NBLK];      // exp(lmax-M)/S

// ---------------------------------------------------------------------------
// helpers
// ---------------------------------------------------------------------------
__device__ __forceinline__ void split_f16(float x, unsigned short &h, unsigned short &l) {
    __half hb = __float2half_rn(x);
    h = __half_as_ushort(hb);
    float r = x - __half2float(hb);
    l = __half_as_ushort(__float2half_rn(r));
}
__device__ __forceinline__ void split_pair_words(float x0, float x1,
                                                 uint32_t &hw, uint32_t &lw) {
    unsigned short h0, l0, h1, l1;
    split_f16(x0, h0, l0);
    split_f16(x1, h1, l1);
    hw = (uint32_t)h0 | ((uint32_t)h1 << 16);
    lw = (uint32_t)l0 | ((uint32_t)l1 << 16);
}
__device__ __forceinline__ uint32_t pack_h2(float x0, float x1) {
    const __half2 h2 = __floats2half2_rn(x0, x1);
    return *(const uint32_t*)&h2;
}

// fp16 inputs, fp32 accumulate
__device__ __forceinline__ void mma_f16(float c[4], const uint32_t a[4],
                                        const uint32_t b0, const uint32_t b1) {
    asm volatile(
        "mma.sync.aligned.m16n8k16.row.col.f32.f16.f16.f32 "
        "{%0,%1,%2,%3}, {%4,%5,%6,%7}, {%8,%9}, {%0,%1,%2,%3};\n"
        : "+f"(c[0]), "+f"(c[1]), "+f"(c[2]), "+f"(c[3])
        : "r"(a[0]), "r"(a[1]), "r"(a[2]), "r"(a[3]),
          "r"(b0), "r"(b1));
}

__device__ __forceinline__ void ldsm4(uint32_t r[4], uint32_t addr) {
    asm volatile("ldmatrix.sync.aligned.m8n8.x4.shared.b16 {%0,%1,%2,%3}, [%4];"
                 : "=r"(r[0]), "=r"(r[1]), "=r"(r[2]), "=r"(r[3]) : "r"(addr));
}
__device__ __forceinline__ void ldsm4t(uint32_t r[4], uint32_t addr) {
    asm volatile("ldmatrix.sync.aligned.m8n8.x4.trans.shared.b16 {%0,%1,%2,%3}, [%4];"
                 : "=r"(r[0]), "=r"(r[1]), "=r"(r[2]), "=r"(r[3]) : "r"(addr));
}
__device__ __forceinline__ void ldsm2(uint32_t r[2], uint32_t addr) {
    asm volatile("ldmatrix.sync.aligned.m8n8.x2.shared.b16 {%0,%1}, [%2];"
                 : "=r"(r[0]), "=r"(r[1]) : "r"(addr));
}
__device__ __forceinline__ void cpasync16(uint32_t saddr, const void* g) {
    asm volatile("cp.async.cg.shared.global [%0], [%1], 16;" :: "r"(saddr), "l"(g));
}
#define CP_COMMIT() asm volatile("cp.async.commit_group;" ::: "memory")
#define CP_WAIT0()  asm volatile("cp.async.wait_group 0;" ::: "memory")

// ---------------------------------------------------------------------------
// Elementwise split: fp32 -> hi/lo fp16 planes (pairs packed in u32).
// ---------------------------------------------------------------------------
__global__ void __launch_bounds__(256) split_pairs(
    const float* __restrict__ src,
    uint32_t* __restrict__ dhi, uint32_t* __restrict__ dlo, size_t npairs)
{
    size_t i = (size_t)blockIdx.x * 256 + threadIdx.x;
    if (i >= npairs) return;
    uint32_t hw, lw;
    split_pair_words(src[2 * i], src[2 * i + 1], hw, lw);
    dhi[i] = hw;
    dlo[i] = lw;
}

// ---------------------------------------------------------------------------
// Elementwise convert: fp32 -> single fp16 plane (pairs packed in u32).
// ---------------------------------------------------------------------------
__global__ void __launch_bounds__(256) cvt_pairs(
    const float* __restrict__ src,
    uint32_t* __restrict__ dst, size_t npairs)
{
    size_t i = (size_t)blockIdx.x * 256 + threadIdx.x;
    if (i >= npairs) return;
    dst[i] = pack_h2(src[2 * i], src[2 * i + 1]);
}

// ---------------------------------------------------------------------------
// Split-fp16 tensor-core GEMM.
//   C[m][n] = sum_k A[m][k] * B[n][k]
// 128x128 CTA tile, 256 threads, 8 warps = 2(m) x 4(n), warp tile 64x32.
// AMODE: 0 = A hi/lo planes R-layout (cp.async + ldsm),
//        1 = A single fp16 plane R-layout (cp.async + ldsm),
//        2 = A is fp32 [k][m] source: LDG + in-register split + T-layout smem
//            + ldmatrix.trans fragments (fuses the transpose+split prepass).
// BSINGLE: B single fp16 plane (1 ldsm2) vs hi/lo split planes.
// OMODE: 0 = fp32 store, 1 = hi/lo split store, 2 = flash softmax epilogue.
// BSCALE: B fragments scaled inline by per-(n, kblock) softmax scales (smem).
// ---------------------------------------------------------------------------
template<bool BIAS, int OMODE, int AMODE, bool BSINGLE, bool BSCALE>
__global__ void __launch_bounds__(256, 2) bgemm(
    const uint32_t* __restrict__ Ahi32, const uint32_t* __restrict__ Alo32,
    int lda, size_t sA,
    const uint32_t* __restrict__ Bhi32, const uint32_t* __restrict__ Blo32,
    int ldb, size_t sB,
    const float* __restrict__ bias,
    float* __restrict__ C, uint32_t* __restrict__ Chi, uint32_t* __restrict__ Clo,
    int ldc, size_t sC, int Ktot,
    float* __restrict__ lmax_out, float* __restrict__ lsum_out,
    const float* __restrict__ bscale)
{
    // A-stage smem words: AMODE2 = 2 planes x 16 k-rows x TPS; else 128 rows x pad
    constexpr int ASTAGE = (AMODE == 2) ? (2 * KC * TPS)
                         : (AMODE == 1) ? (128 * 12) : (128 * 20);
    constexpr int BPS = BSINGLE ? 12 : 20;
    __shared__ uint32_t As[2][ASTAGE];
    __shared__ uint32_t Bs[2][128 * BPS];
    __shared__ float red[OMODE == 2 ? 4 : 1][OMODE == 2 ? 128 : 1];
    __shared__ float sscale[BSCALE ? 128 * NBLK : 1];

    const int bz = blockIdx.z;
    const int tid = threadIdx.x;
    const int m0  = blockIdx.x * 128;
    const int n0  = blockIdx.y * 128;

    // ---- B loader (cp.async): thread -> (row, plane); 2x16B per plane/stage
    const __half* Bhi = (const __half*)Bhi32 + sB * bz;
    const __half* Blo = (const __half*)Blo32 + sB * bz;
    const int lrow = tid >> 1;
    const int lpl  = tid & 1;
    const __half* Bsrc = ((lpl && !BSINGLE) ? Blo : Bhi) + (size_t)(n0 + lrow) * ldb;
    const bool   bload = (!BSINGLE) || (lpl == 0);
    const uint32_t sdstB = (uint32_t)(lrow * BPS + lpl * 8) * 4;

    // ---- A loader ----
    // AMODE 0/1 (cp.async planes)
    const __half* Ahi = (const __half*)Ahi32 + sA * bz;
    const __half* Alo = (const __half*)Alo32 + sA * bz;
    const __half* Asrc = ((lpl && AMODE == 0) ? Alo : Ahi) + (size_t)(m0 + lrow) * lda;
    const bool   aload = (AMODE == 0) || (lpl == 0);
    constexpr int APS = (AMODE == 1) ? 12 : 20;
    const uint32_t sdstA = (uint32_t)(lrow * APS + lpl * 8) * 4;
    // AMODE 2 (fp32 [k][m] LDG + split): thread -> k-row tid>>4, m-seg (tid&15)*8
    const float* Af = (const float*)Ahi32 + sA * bz;
    const int tkr = tid >> 4;
    const int tmc = (tid & 15) * 8;
    const float* Ag = Af + (size_t)tkr * lda + m0 + tmc;
    const uint32_t sdstT = (uint32_t)(tkr * TPS + (tid & 15) * 4) * 4;  // bytes, hi plane

    const uint32_t aS = (uint32_t)__cvta_generic_to_shared(&As[0][0]);
    const uint32_t bS = (uint32_t)__cvta_generic_to_shared(&Bs[0][0]);
    const uint32_t stageA = ASTAGE * 4;
    const uint32_t stageB = 128 * BPS * 4;

    // warp/lane decomposition
    const int wid = tid >> 5, lane = tid & 31;
    const int wm = (wid & 1) * 64;
    const int wn = (wid >> 1) * 32;
    const int qr = lane >> 2, qc = lane & 3;

    // ldmatrix per-lane addresses (byte offsets within a stage)
    uint32_t aoff[4], boff[4];
    {
        if (AMODE == 2) {
            // trans tiles: rows k = (l&7)+(l&16?8:0), m col += (l&8?8:0)
            const int krl = (lane & 7) + ((lane & 16) ? 8 : 0);
            const int mcl = (lane & 8) ? 8 : 0;
            #pragma unroll
            for (int mt = 0; mt < 4; mt++)
                aoff[mt] = (uint32_t)(krl * TPS * 4 + (wm + mt * 16 + mcl) * 2);
        } else {
            const int arl = (lane & 7) + (lane & 8);
            const int awd = (lane & 16) ? 4 : 0;
            #pragma unroll
            for (int mt = 0; mt < 4; mt++)
                aoff[mt] = (uint32_t)(((wm + mt * 16 + arl) * APS + awd) * 4);
        }
        const int brl = lane & 7;
        const int bwd = BSINGLE ? (((lane >> 3) & 1) * 4)
                                : (((lane >> 3) & 3) * 4);
        #pragma unroll
        for (int nt = 0; nt < 4; nt++)
            boff[nt] = (uint32_t)(((wn + nt * 8 + brl) * BPS + bwd) * 4);
    }

    // preload softmax scales for this CTA's n-range
    if (BSCALE) {
        const size_t sb0 = ((size_t)bz * (size_t)(gridDim.y * 128) + n0) * NBLK;
        for (int idx = tid; idx < 128 * NBLK; idx += 256)
            sscale[idx] = bscale[sb0 + idx];
    }

    float acc[4][4][4];
    #pragma unroll
    for (int mt = 0; mt < 4; mt++)
        #pragma unroll
        for (int nt = 0; nt < 4; nt++)
            #pragma unroll
            for (int r = 0; r < 4; r++) acc[mt][nt][r] = 0.f;

    // T-layout STS helper for AMODE2 (8 fp32 -> hi/lo 4+4 words)
    auto sts_trans = [&](int s, float4 v0, float4 v1) {
        uint32_t h[4], l[4];
        split_pair_words(v0.x, v0.y, h[0], l[0]);
        split_pair_words(v0.z, v0.w, h[1], l[1]);
        split_pair_words(v1.x, v1.y, h[2], l[2]);
        split_pair_words(v1.z, v1.w, h[3], l[3]);
        uint32_t* hp = &As[s][0] + (sdstT >> 2);
        *(uint4*)hp              = make_uint4(h[0], h[1], h[2], h[3]);
        *(uint4*)(hp + KC * TPS) = make_uint4(l[0], l[1], l[2], l[3]);
    };

    // ---- prologue: stage 0 ----
    if (AMODE == 2) {
        float4 v0 = *(const float4*)Ag;
        float4 v1 = *(const float4*)(Ag + 4);
        sts_trans(0, v0, v1);
    } else if (aload) {
        cpasync16(aS + sdstA,      Asrc);
        cpasync16(aS + sdstA + 16, Asrc + 8);
    }
    if (bload) {
        cpasync16(bS + sdstB,      Bsrc);
        cpasync16(bS + sdstB + 16, Bsrc + 8);
    }
    CP_COMMIT();
    CP_WAIT0();
    __syncthreads();

    const int nk = Ktot / KC;
    int buf = 0;
    for (int kb = 0; kb < nk; kb++) {
        const bool has_next = (kb + 1) < nk;
        float4 av0, av1;
        if (has_next) {
            const int k0 = (kb + 1) * KC;
            if (AMODE == 2) {
                const float* p = Ag + (size_t)k0 * lda;
                av0 = *(const float4*)p;
                av1 = *(const float4*)(p + 4);
            } else if (aload) {
                const uint32_t ad = aS + (buf ^ 1) * stageA + sdstA;
                cpasync16(ad,      Asrc + k0);
                cpasync16(ad + 16, Asrc + k0 + 8);
            }
            if (bload) {
                const uint32_t bd = bS + (buf ^ 1) * stageB + sdstB;
                cpasync16(bd,      Bsrc + k0);
                cpasync16(bd + 16, Bsrc + k0 + 8);
            }
            CP_COMMIT();
        }

        const uint32_t ab = aS + buf * stageA;
        const uint32_t bb = bS + buf * stageB;

        uint32_t ah[4][4], al[4][4];
        #pragma unroll
        for (int mt = 0; mt < 4; mt++) {
            if (AMODE == 2) {
                ldsm4t(ah[mt], ab + aoff[mt]);
                ldsm4t(al[mt], ab + aoff[mt] + KC * TPS * 4);
            } else {
                ldsm4(ah[mt], ab + aoff[mt]);
                if (AMODE == 0)
                    ldsm4(al[mt], ab + aoff[mt] + 32);
            }
        }
        #pragma unroll
        for (int nt = 0; nt < 4; nt++) {
            if (BSINGLE) {
                uint32_t bv[2];
                ldsm2(bv, bb + boff[nt]);
                if (BSCALE) {
                    const float s = sscale[(wn + nt * 8 + (lane >> 2)) * NBLK + (kb >> 3)];
                    const __half2 hs = __float2half2_rn(s);
                    *(__half2*)&bv[0] = __hmul2(*(const __half2*)&bv[0], hs);
                    *(__half2*)&bv[1] = __hmul2(*(const __half2*)&bv[1], hs);
                }
                if (AMODE != 1) {
                    #pragma unroll
                    for (int mt = 0; mt < 4; mt++)
                        mma_f16(acc[mt][nt], al[mt], bv[0], bv[1]);
                }
                #pragma unroll
                for (int mt = 0; mt < 4; mt++)
                    mma_f16(acc[mt][nt], ah[mt], bv[0], bv[1]);
            } else {
                uint32_t bv[4];
                ldsm4(bv, bb + boff[nt]);
                if (AMODE != 1) {
                    #pragma unroll
                    for (int mt = 0; mt < 4; mt++)
                        mma_f16(acc[mt][nt], ah[mt], bv[2], bv[3]);   // ah*bl
                    #pragma unroll
                    for (int mt = 0; mt < 4; mt++)
                        mma_f16(acc[mt][nt], al[mt], bv[0], bv[1]);   // al*bh
                    #pragma unroll
                    for (int mt = 0; mt < 4; mt++)
                        mma_f16(acc[mt][nt], ah[mt], bv[0], bv[1]);   // ah*bh
                } else {
                    #pragma unroll
                    for (int mt = 0; mt < 4; mt++)
                        mma_f16(acc[mt][nt], ah[mt], bv[2], bv[3]);
                    #pragma unroll
                    for (int mt = 0; mt < 4; mt++)
                        mma_f16(acc[mt][nt], ah[mt], bv[0], bv[1]);
                }
            }
        }

        if (has_next) {
            if (AMODE == 2)
                sts_trans(buf ^ 1, av0, av1);
            CP_WAIT0();
            __syncthreads();
            buf ^= 1;
        }
    }

    // ---- epilogue ----
    if (OMODE == 2) {
        const int wni = wid >> 1;
        float rmax[8];
        #pragma unroll
        for (int j = 0; j < 8; j++) rmax[j] = -FLT_MAX;
        #pragma unroll
        for (int mt = 0; mt < 4; mt++)
            #pragma unroll
            for (int nt = 0; nt < 4; nt++) {
                rmax[mt * 2 + 0] = fmaxf(rmax[mt * 2 + 0],
                                         fmaxf(acc[mt][nt][0], acc[mt][nt][1]));
                rmax[mt * 2 + 1] = fmaxf(rmax[mt * 2 + 1],
                                         fmaxf(acc[mt][nt][2], acc[mt][nt][3]));
            }
        #pragma unroll
        for (int j = 0; j < 8; j++) {
            rmax[j] = fmaxf(rmax[j], __shfl_xor_sync(0xffffffffu, rmax[j], 1));
            rmax[j] = fmaxf(rmax[j], __shfl_xor_sync(0xffffffffu, rmax[j], 2));
        }
        if (qc == 0)
            #pragma unroll
            for (int mt = 0; mt < 4; mt++)
                #pragma unroll
                for (int h = 0; h < 2; h++)
                    red[wni][wm + mt * 16 + qr + 8 * h] = rmax[mt * 2 + h];
        __syncthreads();
        float fm[8];
        #pragma unroll
        for (int mt = 0; mt < 4; mt++)
            #pragma unroll
            for (int h = 0; h < 2; h++) {
                const int rl = wm + mt * 16 + qr + 8 * h;
                fm[mt * 2 + h] = fmaxf(fmaxf(red[0][rl], red[1][rl]),
                                       fmaxf(red[2][rl], red[3][rl]));
            }
        __syncthreads();

        float rs[8];
        #pragma unroll
        for (int j = 0; j < 8; j++) rs[j] = 0.f;
        uint32_t* chb = Chi + (size_t)bz * (sC >> 1);
        #pragma unroll
        for (int mt = 0; mt < 4; mt++)
            #pragma unroll
            for (int nt = 0; nt < 4; nt++) {
                const int col = n0 + wn + nt * 8 + 2 * qc;
                #pragma unroll
                for (int h = 0; h < 2; h++) {
                    const float e0 = __expf(acc[mt][nt][2 * h + 0] - fm[mt * 2 + h]);
                    const float e1 = __expf(acc[mt][nt][2 * h + 1] - fm[mt * 2 + h]);
                    const int row = m0 + wm + mt * 16 + qr + 8 * h;
                    chb[(size_t)row * (ldc >> 1) + (col >> 1)] = pack_h2(e0, e1);
                    rs[mt * 2 + h] += e0 + e1;
                }
            }
        #pragma unroll
        for (int j = 0; j < 8; j++) {
            rs[j] += __shfl_xor_sync(0xffffffffu, rs[j], 1);
            rs[j] += __shfl_xor_sync(0xffffffffu, rs[j], 2);
        }
        if (qc == 0)
            #pragma unroll
            for (int mt = 0; mt < 4; mt++)
                #pragma unroll
                for (int h = 0; h < 2; h++)
                    red[wni][wm + mt * 16 + qr + 8 * h] = rs[mt * 2 + h];
        __syncthreads();
        if (wni == 0 && qc == 0) {
            const size_t mtot = (size_t)gridDim.x * 128;
            #pragma unroll
            for (int mt = 0; mt < 4; mt++)
                #pragma unroll
                for (int h = 0; h < 2; h++) {
                    const int rl = wm + mt * 16 + qr + 8 * h;
                    const float sm = red[0][rl] + red[1][rl] + red[2][rl] + red[3][rl];
                    const size_t o = ((size_t)bz * mtot + m0 + rl) * NBLK + blockIdx.y;
                    lmax_out[o] = fm[mt * 2 + h];
                    lsum_out[o] = sm;
                }
        }
    } else {
        #pragma unroll
        for (int mt = 0; mt < 4; mt++) {
            #pragma unroll
            for (int nt = 0; nt < 4; nt++) {
                const int row = m0 + wm + mt * 16 + qr;
                const int col = n0 + wn + nt * 8 + 2 * qc;
                float v0 = acc[mt][nt][0], v1 = acc[mt][nt][1];
                float v2 = acc[mt][nt][2], v3 = acc[mt][nt][3];
                if (BIAS) {
                    const float b0 = bias[col], b1 = bias[col + 1];
                    v0 += b0; v1 += b1; v2 += b0; v3 += b1;
                }
                if (OMODE == 1) {
                    uint32_t* chb = Chi + (size_t)bz * (sC >> 1);
                    uint32_t* clb = Clo + (size_t)bz * (sC >> 1);
                    uint32_t hw, lw;
                    split_pair_words(v0, v1, hw, lw);
                    size_t o = (size_t)row * (ldc >> 1) + (col >> 1);
                    chb[o] = hw; clb[o] = lw;
                    split_pair_words(v2, v3, hw, lw);
                    o = (size_t)(row + 8) * (ldc >> 1) + (col >> 1);
                    chb[o] = hw; clb[o] = lw;
                } else {
                    float* cb = C + sC * bz;
                    *(float2*)&cb[(size_t)row * ldc + col]       = make_float2(v0, v1);
                    *(float2*)&cb[(size_t)(row + 8) * ldc + col] = make_float2(v2, v3);
                }
            }
        }
    }
}

// ---------------------------------------------------------------------------
// Combine per-block softmax stats -> per-(row, block) scale = exp(lmax-M)/S.
// ---------------------------------------------------------------------------
__global__ void __launch_bounds__(256) combine_stats(
    const float* __restrict__ lmax, const float* __restrict__ lsum,
    float* __restrict__ scale)
{
    const int r = blockIdx.x * 256 + threadIdx.x;
    if (r >= BB * NP) return;
    const float* lm = lmax + (size_t)r * NBLK;
    const float* ls = lsum + (size_t)r * NBLK;
    float M = -FLT_MAX;
    #pragma unroll
    for (int j = 0; j < NBLK; j++) M = fmaxf(M, lm[j]);
    float e[NBLK], S = 0.f;
    #pragma unroll
    for (int j = 0; j < NBLK; j++) {
        e[j] = __expf(lm[j] - M);
        S += ls[j] * e[j];
    }
    const float inv = 1.0f / S;
    float* sc = scale + (size_t)r * NBLK;
    #pragma unroll
    for (int j = 0; j < NBLK; j++) sc[j] = e[j] * inv;
}

// ---------------------------------------------------------------------------
extern "C" void kernel_launch(void* const* d_in, const int* in_sizes, int n_in,
                              void* d_out, int out_size)
{
    const float* qf = (const float*)d_in[0];   // [B, CQ, 48, 48]
    const float* rf = (const float*)d_in[1];   // [B, CR, 48, 48]
    const float* Wq = (const float*)d_in[2];   // [HID, CQ]
    const float* bq = (const float*)d_in[3];   // [HID]
    const float* Wk = (const float*)d_in[4];   // [HID, CR]
    const float* bk = (const float*)d_in[5];   // [HID]
    float* out = (float*)d_out;                // [B, CR, 48, 48]

    uint32_t *rfS, *Wqh, *Wql, *Wkh, *Wkl, *Qh, *Ql, *Kh, *Kl, *ath;
    float *lmx, *lsm, *scl;
    cudaGetSymbolAddress((void**)&rfS, g_rfS);
    cudaGetSymbolAddress((void**)&Wqh, g_Wq_hi);
    cudaGetSymbolAddress((void**)&Wql, g_Wq_lo);
    cudaGetSymbolAddress((void**)&Wkh, g_Wk_hi);
    cudaGetSymbolAddress((void**)&Wkl, g_Wk_lo);
    cudaGetSymbolAddress((void**)&Qh, g_Q_hi);
    cudaGetSymbolAddress((void**)&Ql, g_Q_lo);
    cudaGetSymbolAddress((void**)&Kh, g_K_hi);
    cudaGetSymbolAddress((void**)&Kl, g_K_lo);
    cudaGetSymbolAddress((void**)&ath, g_at);
    cudaGetSymbolAddress((void**)&lmx, g_lmax);
    cudaGetSymbolAddress((void**)&lsm, g_lsum);
    cudaGetSymbolAddress((void**)&scl, g_scale);

    // ---- prepass: weight splits + V convert (transposes now fused in GEMM1/2)
    {
        size_t np;
        np = (size_t)HID * CQ / 2;
        split_pairs<<<(unsigned)((np + 255) / 256), 256>>>(Wq, Wqh, Wql, np);
        np = (size_t)HID * CR / 2;
        split_pairs<<<(unsigned)((np + 255) / 256), 256>>>(Wk, Wkh, Wkl, np);
        np = (size_t)BB * CR * NP / 2;
        cvt_pairs<<<(unsigned)((np + 255) / 256), 256>>>(rf, rfS, np);
    }

    // ---- GEMM1: Q[i][o] = qf[c][i] * Wq[o][c] + bq -> hi/lo planes
    //      (A = fp32 [k=c][m=i], fused transpose+split loader) ----
    bgemm<true, 1, 2, false, false><<<dim3(NP / 128, HID / 128, BB), 256>>>(
        (const uint32_t*)qf, nullptr, NP, (size_t)CQ * NP,
        Wqh, Wql, CQ, 0,
        bq,
        nullptr, Qh, Ql, HID, (size_t)NP * HID,
        CQ, nullptr, nullptr, nullptr);

    // ---- GEMM2: K[p][o] = rf[c][p] * Wk[o][c] + bk -> hi/lo planes ----
    bgemm<true, 1, 2, false, false><<<dim3(NP / 128, HID / 128, BB), 256>>>(
        (const uint32_t*)rf, nullptr, NP, (size_t)CR * NP,
        Wkh, Wkl, CR, 0,
        bk,
        nullptr, Kh, Kl, HID, (size_t)NP * HID,
        CR, nullptr, nullptr, nullptr);

    // ---- GEMM3: S[i][p] = Q[i][k] * K[p][k]; flash epilogue ----
    bgemm<false, 2, 0, false, false><<<dim3(NP / 128, NP / 128, BB), 256>>>(
        Qh, Ql, HID, (size_t)NP * HID,
        Kh, Kl, HID, (size_t)NP * HID,
        nullptr,
        nullptr, ath, nullptr, NP, (size_t)NP * NP,
        HID, lmx, lsm, nullptr);

    // ---- combine per-block stats -> scales ----
    combine_stats<<<(BB * NP + 255) / 256, 256>>>(lmx, lsm, scl);

    // ---- GEMM4: out[c][i] = V[c][p] * exp[i][p] * scale[i][blk(p)] ----
    bgemm<false, 0, 1, true, true><<<dim3(CR / 128, NP / 128, BB), 256>>>(
        rfS, rfS, NP, (size_t)CR * NP,
        ath, ath, NP, (size_t)NP * NP,
        nullptr,
        out, nullptr, nullptr, NP, (size_t)CR * NP,
        NP, nullptr, nullptr, scl);
}